// round 6
// baseline (speedup 1.0000x reference)
#include <cuda_runtime.h>
#include <cuda_bf16.h>
#include <math.h>
#include <stdint.h>

#define NN 50000
#define EMAX 500000

// ---------------- scratch (device globals; no allocations allowed) ----------
// Split per-node features. A = dst-side, B = src-side. Stride 8*O bytes:
//   [0   ,2O ) q  bf16[O]
//   [2O  ,4O ) k  bf16[O]
//   [4O  ,8O ) v  f32 [O]
__device__ __align__(16) unsigned char g_featA[NN * 1024];
__device__ __align__(16) unsigned char g_featB[NN * 1024];
__device__ float g_x0[NN * 128];      // relu(layer0 out) f32 (residual + L1 GEMM input)
__device__ float g_h1[NN * 64];       // relu(layer1 out) f32 (L2 GEMM input)
__device__ float g_wcatT[768 * 128];  // transposed transformed weights [M][K], tf32
__device__ float g_bcat[768];         // concatenated bias (bias only on A columns)
// counting-sort scratch
__device__ int g_hist[NN];
__device__ int g_binoff[NN + 1];
__device__ int g_cursor[NN];
__device__ int g_ssrc[EMAX];

__device__ __forceinline__ float rna_tf32(float v) {
    float o;
    asm("cvt.rna.tf32.f32 %0, %1;" : "=f"(o) : "f"(v));
    return o;
}
__device__ __forceinline__ float ex2f(float v) {
    float o;
    asm("ex2.approx.f32 %0, %1;" : "=f"(o) : "f"(v));
    return o;
}

// ---------------- build W_catT[col][c] = rna([Wtop-Wbot | Wbot]); zero hist --
__global__ void build_wcat(const float* __restrict__ wq, const float* __restrict__ wk,
                           const float* __restrict__ wv, const float* __restrict__ bq,
                           const float* __restrict__ bk, const float* __restrict__ bv,
                           int C, int O) {
    int M = 6 * O;
    int idx = blockIdx.x * blockDim.x + threadIdx.x;
    if (idx < C * M) {
        int c = idx / M, col = idx % M;
        int grp = col / O, j = col % O;
        const float* w = (grp < 2) ? wq : (grp < 4 ? wk : wv);
        float top = w[c * O + j];
        float bot = w[(C + c) * O + j];
        float val = (grp & 1) ? bot : (top - bot);
        g_wcatT[(size_t)col * C + c] = rna_tf32(val);
    }
    if (idx < M) {
        int grp = idx / O, j = idx % O;
        const float* b = (grp < 2) ? bq : (grp < 4 ? bk : bv);
        g_bcat[idx] = (grp & 1) ? 0.0f : b[j];
    }
    if (idx < NN) g_hist[idx] = 0;  // prepare histogram for this layer's sort
}

// ---------------- counting sort: hist -> scan -> scatter ---------------------
__global__ void hist_kernel(const int* __restrict__ edst, int E) {
    int i = blockIdx.x * blockDim.x + threadIdx.x;
    if (i < E) atomicAdd(&g_hist[edst[i]], 1);
}

__global__ void scan_kernel() {
    __shared__ int sh[1024];
    int t = threadIdx.x;
    const int chunk = (NN + 1023) / 1024;  // 49
    int beg = t * chunk;
    int end = min(beg + chunk, NN);
    int s = 0;
    for (int i = beg; i < end; i++) s += g_hist[i];
    sh[t] = s;
    __syncthreads();
    for (int off = 1; off < 1024; off <<= 1) {
        int v = (t >= off) ? sh[t - off] : 0;
        __syncthreads();
        if (t >= off) sh[t] += v;
        __syncthreads();
    }
    int run = (t == 0) ? 0 : sh[t - 1];
    for (int i = beg; i < end; i++) {
        int h = g_hist[i];
        g_binoff[i] = run;
        g_cursor[i] = run;
        run += h;
    }
    if (t == 1023) g_binoff[NN] = run;
}

__global__ void scatter_kernel(const int* __restrict__ esrc,
                               const int* __restrict__ edst, int E) {
    int i = blockIdx.x * blockDim.x + threadIdx.x;
    if (i < E) {
        int d = edst[i];
        int pos = atomicAdd(&g_cursor[d], 1);
        g_ssrc[pos] = esrc[i];
    }
}

// ---------------- tf32 tensor-core GEMM --------------------------------------
// feat = A(NxK) @ g_wcatT^T + bias, written to split A/B node layout.
// srcsel: 0 -> Aext (layer-0 input x), 1 -> g_x0, 2 -> g_h1.
template <int K, int O>
__global__ __launch_bounds__(256, 2) void mma_gemm(const float* __restrict__ Aext,
                                                   int srcsel, int N) {
    const float* A = (srcsel == 0) ? Aext : ((srcsel == 1) ? g_x0 : g_h1);
    constexpr int PAD = 20;
    __shared__ float As[2][128 * PAD];
    __shared__ float Bs[2][128 * PAD];

    const int tid = threadIdx.x;
    const int lane = tid & 31;
    const int wid = tid >> 5;
    const int wm = (wid & 1) * 64;
    const int wn = (wid >> 1) * 32;
    const int bm = blockIdx.y * 128;
    const int bn = blockIdx.x * 128;

    float acc[4][4][4];
#pragma unroll
    for (int a = 0; a < 4; a++)
#pragma unroll
        for (int b = 0; b < 4; b++)
#pragma unroll
            for (int c = 0; c < 4; c++) acc[a][b][c] = 0.0f;

    const int r_ld = tid >> 1;
    const int ch0 = (tid & 1) * 2;
    const int garow = bm + r_ld;
    const float* aptr = A + (size_t)(garow < N ? garow : 0) * K;
    const int asz = (garow < N) ? 16 : 0;
    const float* bptr = g_wcatT + (size_t)(bn + r_ld) * K;

#define SMADDR(p) ((uint32_t)__cvta_generic_to_shared(p))

#define LOAD_STAGE(buf, k0)                                                          \
    {                                                                                \
        _Pragma("unroll") for (int i = 0; i < 2; i++) {                              \
            int ch = ch0 + i;                                                        \
            asm volatile("cp.async.cg.shared.global [%0], [%1], 16, %2;" ::"r"(      \
                             SMADDR(&As[buf][r_ld * PAD + ch * 4])),                 \
                         "l"(aptr + (k0) + ch * 4), "r"(asz));                       \
            asm volatile("cp.async.cg.shared.global [%0], [%1], 16;" ::"r"(          \
                             SMADDR(&Bs[buf][r_ld * PAD + ch * 4])),                 \
                         "l"(bptr + (k0) + ch * 4));                                 \
        }                                                                            \
        asm volatile("cp.async.commit_group;");                                      \
    }

    LOAD_STAGE(0, 0);
    constexpr int NIT = K / 16;
#pragma unroll
    for (int it = 0; it < NIT; it++) {
        const int buf = it & 1;
        if (it + 1 < NIT) {
            LOAD_STAGE(buf ^ 1, (it + 1) * 16);
            asm volatile("cp.async.wait_group 1;");
        } else {
            asm volatile("cp.async.wait_group 0;");
        }
        __syncthreads();

#pragma unroll
        for (int ks = 0; ks < 16; ks += 8) {
            uint32_t af[4][4];
#pragma unroll
            for (int mt = 0; mt < 4; mt++) {
                const float* p = &As[buf][(wm + mt * 16 + (lane & 15)) * PAD + ks +
                                          (lane >> 4) * 4];
                asm volatile(
                    "ldmatrix.sync.aligned.m8n8.x4.shared.b16 {%0,%1,%2,%3}, [%4];"
                    : "=r"(af[mt][0]), "=r"(af[mt][1]), "=r"(af[mt][2]), "=r"(af[mt][3])
                    : "r"(SMADDR(p)));
#pragma unroll
                for (int r = 0; r < 4; r++)
                    af[mt][r] = __float_as_uint(rna_tf32(__uint_as_float(af[mt][r])));
            }
            uint32_t bf[2][4];
#pragma unroll
            for (int bi = 0; bi < 2; bi++) {
                const float* p = &Bs[buf][(wn + bi * 16 + (lane & 7) +
                                           ((lane >> 4) << 3)) *
                                              PAD +
                                          ks + ((lane >> 3) & 1) * 4];
                asm volatile(
                    "ldmatrix.sync.aligned.m8n8.x4.shared.b16 {%0,%1,%2,%3}, [%4];"
                    : "=r"(bf[bi][0]), "=r"(bf[bi][1]), "=r"(bf[bi][2]), "=r"(bf[bi][3])
                    : "r"(SMADDR(p)));
            }
#pragma unroll
            for (int mt = 0; mt < 4; mt++)
#pragma unroll
                for (int nt = 0; nt < 4; nt++) {
                    uint32_t b0 = bf[nt >> 1][(nt & 1) * 2];
                    uint32_t b1 = bf[nt >> 1][(nt & 1) * 2 + 1];
                    asm volatile(
                        "mma.sync.aligned.m16n8k8.row.col.f32.tf32.tf32.f32 "
                        "{%0,%1,%2,%3}, {%4,%5,%6,%7}, {%8,%9}, {%0,%1,%2,%3};"
                        : "+f"(acc[mt][nt][0]), "+f"(acc[mt][nt][1]),
                          "+f"(acc[mt][nt][2]), "+f"(acc[mt][nt][3])
                        : "r"(af[mt][0]), "r"(af[mt][1]), "r"(af[mt][2]),
                          "r"(af[mt][3]), "r"(b0), "r"(b1));
                }
        }
        __syncthreads();
    }

    // Epilogue: add bias, write split A/B mixed-precision layout.
#pragma unroll
    for (int mt = 0; mt < 4; mt++) {
        int r = bm + wm + mt * 16 + (lane >> 2);
#pragma unroll
        for (int half = 0; half < 2; half++) {
            int rr = r + half * 8;
            if (rr < N) {
                unsigned char* baseA = g_featA + (size_t)rr * (8 * O);
                unsigned char* baseB = g_featB + (size_t)rr * (8 * O);
#pragma unroll
                for (int nt = 0; nt < 4; nt++) {
                    int c = bn + wn + nt * 8 + (lane & 3) * 2;
                    int grp = c / O;
                    int j = c - grp * O;
                    float ox = acc[mt][nt][half * 2 + 0] + g_bcat[c];
                    float oy = acc[mt][nt][half * 2 + 1] + g_bcat[c + 1];
                    unsigned char* base = (grp & 1) ? baseB : baseA;
                    int reg = grp >> 1;  // 0=q, 1=k, 2=v
                    if (reg < 2) {
                        __nv_bfloat162 h2 = __floats2bfloat162_rn(ox, oy);
                        *(__nv_bfloat162*)(base + reg * (2 * O) + j * 2) = h2;
                    } else {
                        *(float2*)(base + 4 * O + j * 4) = make_float2(ox, oy);
                    }
                }
            }
        }
    }
#undef LOAD_STAGE
#undef SMADDR
}

// ---------------- node kernel: warp per dst, head-per-thread, 4 edge slots ---
// lane = slot*8 + head. Each thread owns ONE full head (hs channels) ->
// softmax is thread-local (no in-loop shuffles). The 4 slots process 4 edges
// concurrently (4 independent gather chains). Slot accumulators combined at end.
// mode 0: g_x0 = relu(mean); mode 1: g_h1 = relu(mean); mode 2: out = relu(mean+g_x0)
template <int O>
__global__ __launch_bounds__(256) void node_kernel(float* __restrict__ outp, int mode) {
    constexpr int HS = O / 8;    // 16 or 8 channels per head
    constexpr int HS2 = HS / 2;  // bf16x2 regs per q/k vector
    constexpr int NQ = HS / 8;   // uint4 (16B) loads for q or k: 2 or 1
    constexpr int NV = HS / 4;   // float4 loads for v: 4 or 2
    const float CEXP = ((O == 128) ? 0.25f : 0.3535533905932738f) * 1.44269504f;

    int d = (blockIdx.x * blockDim.x + threadIdx.x) >> 5;
    int lane = threadIdx.x & 31;
    if (d >= NN) return;
    int slot = lane >> 3;   // 0..3 edge slot
    int head = lane & 7;    // 0..7

    int beg = g_binoff[d];
    int end = g_binoff[d + 1];
    const unsigned char* fa = g_featA + (size_t)d * (8 * O);
    const int qoff = head * HS * 2;       // byte offset into q (bf16)
    const int voff = head * HS * 4;       // byte offset into v (f32)

    uint4 qa[NQ], ka[NQ];
    float va[HS], acc[HS];
#pragma unroll
    for (int i = 0; i < NQ; i++) {
        qa[i] = __ldg((const uint4*)(fa + qoff + i * 16));
        ka[i] = __ldg((const uint4*)(fa + 2 * O + qoff + i * 16));
    }
#pragma unroll
    for (int i = 0; i < NV; i++)
        *(float4*)(va + i * 4) = __ldg((const float4*)(fa + 4 * O + voff + i * 16));
#pragma unroll
    for (int i = 0; i < HS; i++) acc[i] = 0.0f;

    for (int j = beg + slot; j < end; j += 4) {
        int s = __ldg(&g_ssrc[j]);
        const unsigned char* fb = g_featB + (size_t)s * (8 * O);
        uint4 qb[NQ], kb[NQ];
        float vb[HS];
#pragma unroll
        for (int i = 0; i < NQ; i++) {
            qb[i] = __ldg((const uint4*)(fb + qoff + i * 16));
            kb[i] = __ldg((const uint4*)(fb + 2 * O + qoff + i * 16));
        }
#pragma unroll
        for (int i = 0; i < NV; i++)
            *(float4*)(vb + i * 4) = __ldg((const float4*)(fb + 4 * O + voff + i * 16));

        float z[HS];
#pragma unroll
        for (int h = 0; h < HS2; h++) {
            __nv_bfloat162 a2 = ((const __nv_bfloat162*)qa)[h];
            __nv_bfloat162 b2 = ((const __nv_bfloat162*)qb)[h];
            __nv_bfloat162 c2 = ((const __nv_bfloat162*)ka)[h];
            __nv_bfloat162 d2 = ((const __nv_bfloat162*)kb)[h];
            __nv_bfloat162 t = __hmul2(__hadd2(a2, b2), __hadd2(c2, d2));
            float2 f = __bfloat1622float2(t);
            z[2 * h] = f.x;
            z[2 * h + 1] = f.y;
        }
        float m = z[0];
#pragma unroll
        for (int i = 1; i < HS; i++) m = fmaxf(m, z[i]);

        float p[HS], sum = 0.0f;
#pragma unroll
        for (int i = 0; i < HS; i++) {
            p[i] = ex2f((z[i] - m) * CEXP);
            sum += p[i];
        }

        int dd = abs(d - s);
        float ew = (dd > 8) ? 1.0f : ((dd == 8) ? 0.0f : -1.0f);
        float w = ew / sum;
#pragma unroll
        for (int i = 0; i < HS; i++) acc[i] = fmaf(p[i] * w, va[i] + vb[i], acc[i]);
    }

    // combine the 4 slot accumulators (lanes differing in bits 3,4)
#pragma unroll
    for (int i = 0; i < HS; i++) {
        acc[i] += __shfl_xor_sync(0xFFFFFFFFu, acc[i], 8);
        acc[i] += __shfl_xor_sync(0xFFFFFFFFu, acc[i], 16);
    }

    if (slot == 0) {
        float invdeg = 1.0f / (float)max(end - beg, 1);
        int idx0 = d * O + head * HS;
        if (mode == 2) {
#pragma unroll
            for (int i = 0; i < NV; i++) {
                float4 r = *(const float4*)(g_x0 + idx0 + i * 4);
                float4 o;
                o.x = fmaxf(acc[i * 4 + 0] * invdeg + r.x, 0.0f);
                o.y = fmaxf(acc[i * 4 + 1] * invdeg + r.y, 0.0f);
                o.z = fmaxf(acc[i * 4 + 2] * invdeg + r.z, 0.0f);
                o.w = fmaxf(acc[i * 4 + 3] * invdeg + r.w, 0.0f);
                *(float4*)(outp + idx0 + i * 4) = o;
            }
        } else {
            float* dst = (mode == 0) ? g_x0 : g_h1;
#pragma unroll
            for (int i = 0; i < NV; i++) {
                float4 o;
                o.x = fmaxf(acc[i * 4 + 0] * invdeg, 0.0f);
                o.y = fmaxf(acc[i * 4 + 1] * invdeg, 0.0f);
                o.z = fmaxf(acc[i * 4 + 2] * invdeg, 0.0f);
                o.w = fmaxf(acc[i * 4 + 3] * invdeg, 0.0f);
                *(float4*)(dst + idx0 + i * 4) = o;
            }
        }
    }
}

// ---------------- launch -----------------------------------------------------
extern "C" void kernel_launch(void* const* d_in, const int* in_sizes, int n_in,
                              void* d_out, int out_size) {
    const float* x = (const float*)d_in[0];
    const int* e0 = (const int*)d_in[1];
    const int* e1 = (const int*)d_in[2];
    const int* e2 = (const int*)d_in[3];
    const float* wq0 = (const float*)d_in[5];
    const float* bq0 = (const float*)d_in[6];
    const float* wk0 = (const float*)d_in[7];
    const float* bk0 = (const float*)d_in[8];
    const float* wv0 = (const float*)d_in[9];
    const float* bv0 = (const float*)d_in[10];
    const float* wq1 = (const float*)d_in[11];
    const float* bq1 = (const float*)d_in[12];
    const float* wk1 = (const float*)d_in[13];
    const float* bk1 = (const float*)d_in[14];
    const float* wv1 = (const float*)d_in[15];
    const float* bv1 = (const float*)d_in[16];
    const float* wq2 = (const float*)d_in[17];
    const float* bq2 = (const float*)d_in[18];
    const float* wk2 = (const float*)d_in[19];
    const float* bk2 = (const float*)d_in[20];
    const float* wv2 = (const float*)d_in[21];
    const float* bv2 = (const float*)d_in[22];

    int E0 = in_sizes[1] / 2;
    int E1 = in_sizes[2] / 2;
    int E2 = in_sizes[3] / 2;

    int nblk = (NN + 127) / 128;
    int nodeGrid = (NN * 32 + 255) / 256;  // warp per node
    int bw0 = (128 * 768 + 255) / 256;
    int bw1 = max((128 * 384 + 255) / 256, (NN + 255) / 256);
    int bw2 = max((64 * 768 + 255) / 256, (NN + 255) / 256);

    // ---- Layer 0: C=128, O=128 ----
    build_wcat<<<bw0, 256>>>(wq0, wk0, wv0, bq0, bk0, bv0, 128, 128);
    hist_kernel<<<(E0 + 255) / 256, 256>>>(e0 + E0, E0);
    scan_kernel<<<1, 1024>>>();
    scatter_kernel<<<(E0 + 255) / 256, 256>>>(e0, e0 + E0, E0);
    mma_gemm<128, 128><<<dim3(6, nblk), 256>>>(x, 0, NN);
    node_kernel<128><<<nodeGrid, 256>>>(nullptr, 0);

    // ---- Layer 1: C=128, O=64 ----
    build_wcat<<<bw1, 256>>>(wq1, wk1, wv1, bq1, bk1, bv1, 128, 64);
    hist_kernel<<<(E1 + 255) / 256, 256>>>(e1 + E1, E1);
    scan_kernel<<<1, 1024>>>();
    scatter_kernel<<<(E1 + 255) / 256, 256>>>(e1, e1 + E1, E1);
    mma_gemm<128, 64><<<dim3(3, nblk), 256>>>(nullptr, 1, NN);
    node_kernel<64><<<nodeGrid, 256>>>(nullptr, 1);

    // ---- Layer 2: C=64, O=128 ----
    build_wcat<<<bw2, 256>>>(wq2, wk2, wv2, bq2, bk2, bv2, 64, 128);
    hist_kernel<<<(E2 + 255) / 256, 256>>>(e2 + E2, E2);
    scan_kernel<<<1, 1024>>>();
    scatter_kernel<<<(E2 + 255) / 256, 256>>>(e2, e2 + E2, E2);
    mma_gemm<64, 128><<<dim3(6, nblk), 256>>>(nullptr, 2, NN);
    node_kernel<128><<<nodeGrid, 256>>>((float*)d_out, 2);
}

// round 7
// speedup vs baseline: 1.3026x; 1.3026x over previous
#include <cuda_runtime.h>
#include <cuda_bf16.h>
#include <math.h>
#include <stdint.h>

#define NN 50000

// ---------------- scratch (device globals; no allocations allowed) ----------
// Split per-node features. A = dst-side, B = src-side. Stride 8*O bytes:
//   [0   ,2O ) q  bf16[O]
//   [2O  ,4O ) k  bf16[O]
//   [4O  ,8O ) v  f32 [O]
__device__ __align__(16) unsigned char g_featA[NN * 1024];
__device__ __align__(16) unsigned char g_featB[NN * 1024];
__device__ float g_x0[NN * 128];      // relu(layer0 out) f32 (residual + L1 GEMM input)
__device__ float g_h1[NN * 64];       // relu(layer1 out) f32 (L2 GEMM input)
__device__ float g_acc[NN * 128];     // edge-aggregation accumulator
__device__ float g_cnt[NN];           // edge count per dst
__device__ float g_wcatT[768 * 128];  // transposed transformed weights [M][K], tf32
__device__ float g_bcat[768];         // concatenated bias (bias only on A columns)

__device__ __forceinline__ float rna_tf32(float v) {
    float o;
    asm("cvt.rna.tf32.f32 %0, %1;" : "=f"(o) : "f"(v));
    return o;
}
__device__ __forceinline__ float ex2f(float v) {
    float o;
    asm("ex2.approx.f32 %0, %1;" : "=f"(o) : "f"(v));
    return o;
}

// ---------------- build W_catT[col][c] = rna([Wtop-Wbot | Wbot]); zero cnt ---
__global__ void build_wcat(const float* __restrict__ wq, const float* __restrict__ wk,
                           const float* __restrict__ wv, const float* __restrict__ bq,
                           const float* __restrict__ bk, const float* __restrict__ bv,
                           int C, int O) {
    int M = 6 * O;
    int idx = blockIdx.x * blockDim.x + threadIdx.x;
    if (idx < C * M) {
        int c = idx / M, col = idx % M;
        int grp = col / O, j = col % O;
        const float* w = (grp < 2) ? wq : (grp < 4 ? wk : wv);
        float top = w[c * O + j];
        float bot = w[(C + c) * O + j];
        float val = (grp & 1) ? bot : (top - bot);
        g_wcatT[(size_t)col * C + c] = rna_tf32(val);
    }
    if (idx < M) {
        int grp = idx / O, j = idx % O;
        const float* b = (grp < 2) ? bq : (grp < 4 ? bk : bv);
        g_bcat[idx] = (grp & 1) ? 0.0f : b[j];
    }
    if (idx < NN) g_cnt[idx] = 0.0f;  // prepare edge-count for this layer
}

// ---------------- one-time acc zero ------------------------------------------
__global__ void zero_acc(int n) {
    int idx = blockIdx.x * blockDim.x + threadIdx.x;
    if (idx < n) g_acc[idx] = 0.0f;
}

// ---------------- tf32 tensor-core GEMM --------------------------------------
// feat = A(NxK) @ g_wcatT^T + bias, written to split A/B node layout.
// srcsel: 0 -> Aext (layer-0 input x), 1 -> g_x0, 2 -> g_h1.
template <int K, int O>
__global__ __launch_bounds__(256, 2) void mma_gemm(const float* __restrict__ Aext,
                                                   int srcsel, int N) {
    const float* A = (srcsel == 0) ? Aext : ((srcsel == 1) ? g_x0 : g_h1);
    constexpr int PAD = 20;
    __shared__ float As[2][128 * PAD];
    __shared__ float Bs[2][128 * PAD];

    const int tid = threadIdx.x;
    const int lane = tid & 31;
    const int wid = tid >> 5;
    const int wm = (wid & 1) * 64;
    const int wn = (wid >> 1) * 32;
    const int bm = blockIdx.y * 128;
    const int bn = blockIdx.x * 128;

    float acc[4][4][4];
#pragma unroll
    for (int a = 0; a < 4; a++)
#pragma unroll
        for (int b = 0; b < 4; b++)
#pragma unroll
            for (int c = 0; c < 4; c++) acc[a][b][c] = 0.0f;

    const int r_ld = tid >> 1;
    const int ch0 = (tid & 1) * 2;
    const int garow = bm + r_ld;
    const float* aptr = A + (size_t)(garow < N ? garow : 0) * K;
    const int asz = (garow < N) ? 16 : 0;
    const float* bptr = g_wcatT + (size_t)(bn + r_ld) * K;

#define SMADDR(p) ((uint32_t)__cvta_generic_to_shared(p))

#define LOAD_STAGE(buf, k0)                                                          \
    {                                                                                \
        _Pragma("unroll") for (int i = 0; i < 2; i++) {                              \
            int ch = ch0 + i;                                                        \
            asm volatile("cp.async.cg.shared.global [%0], [%1], 16, %2;" ::"r"(      \
                             SMADDR(&As[buf][r_ld * PAD + ch * 4])),                 \
                         "l"(aptr + (k0) + ch * 4), "r"(asz));                       \
            asm volatile("cp.async.cg.shared.global [%0], [%1], 16;" ::"r"(          \
                             SMADDR(&Bs[buf][r_ld * PAD + ch * 4])),                 \
                         "l"(bptr + (k0) + ch * 4));                                 \
        }                                                                            \
        asm volatile("cp.async.commit_group;");                                      \
    }

    LOAD_STAGE(0, 0);
    constexpr int NIT = K / 16;
#pragma unroll
    for (int it = 0; it < NIT; it++) {
        const int buf = it & 1;
        if (it + 1 < NIT) {
            LOAD_STAGE(buf ^ 1, (it + 1) * 16);
            asm volatile("cp.async.wait_group 1;");
        } else {
            asm volatile("cp.async.wait_group 0;");
        }
        __syncthreads();

#pragma unroll
        for (int ks = 0; ks < 16; ks += 8) {
            uint32_t af[4][4];
#pragma unroll
            for (int mt = 0; mt < 4; mt++) {
                const float* p = &As[buf][(wm + mt * 16 + (lane & 15)) * PAD + ks +
                                          (lane >> 4) * 4];
                asm volatile(
                    "ldmatrix.sync.aligned.m8n8.x4.shared.b16 {%0,%1,%2,%3}, [%4];"
                    : "=r"(af[mt][0]), "=r"(af[mt][1]), "=r"(af[mt][2]), "=r"(af[mt][3])
                    : "r"(SMADDR(p)));
#pragma unroll
                for (int r = 0; r < 4; r++)
                    af[mt][r] = __float_as_uint(rna_tf32(__uint_as_float(af[mt][r])));
            }
            uint32_t bf[2][4];
#pragma unroll
            for (int bi = 0; bi < 2; bi++) {
                const float* p = &Bs[buf][(wn + bi * 16 + (lane & 7) +
                                           ((lane >> 4) << 3)) *
                                              PAD +
                                          ks + ((lane >> 3) & 1) * 4];
                asm volatile(
                    "ldmatrix.sync.aligned.m8n8.x4.shared.b16 {%0,%1,%2,%3}, [%4];"
                    : "=r"(bf[bi][0]), "=r"(bf[bi][1]), "=r"(bf[bi][2]), "=r"(bf[bi][3])
                    : "r"(SMADDR(p)));
            }
#pragma unroll
            for (int mt = 0; mt < 4; mt++)
#pragma unroll
                for (int nt = 0; nt < 4; nt++) {
                    uint32_t b0 = bf[nt >> 1][(nt & 1) * 2];
                    uint32_t b1 = bf[nt >> 1][(nt & 1) * 2 + 1];
                    asm volatile(
                        "mma.sync.aligned.m16n8k8.row.col.f32.tf32.tf32.f32 "
                        "{%0,%1,%2,%3}, {%4,%5,%6,%7}, {%8,%9}, {%0,%1,%2,%3};"
                        : "+f"(acc[mt][nt][0]), "+f"(acc[mt][nt][1]),
                          "+f"(acc[mt][nt][2]), "+f"(acc[mt][nt][3])
                        : "r"(af[mt][0]), "r"(af[mt][1]), "r"(af[mt][2]),
                          "r"(af[mt][3]), "r"(b0), "r"(b1));
                }
        }
        __syncthreads();
    }

    // Epilogue: add bias, write split A/B mixed-precision layout.
#pragma unroll
    for (int mt = 0; mt < 4; mt++) {
        int r = bm + wm + mt * 16 + (lane >> 2);
#pragma unroll
        for (int half = 0; half < 2; half++) {
            int rr = r + half * 8;
            if (rr < N) {
                unsigned char* baseA = g_featA + (size_t)rr * (8 * O);
                unsigned char* baseB = g_featB + (size_t)rr * (8 * O);
#pragma unroll
                for (int nt = 0; nt < 4; nt++) {
                    int c = bn + wn + nt * 8 + (lane & 3) * 2;
                    int grp = c / O;
                    int j = c - grp * O;
                    float ox = acc[mt][nt][half * 2 + 0] + g_bcat[c];
                    float oy = acc[mt][nt][half * 2 + 1] + g_bcat[c + 1];
                    unsigned char* base = (grp & 1) ? baseB : baseA;
                    int reg = grp >> 1;  // 0=q, 1=k, 2=v
                    if (reg < 2) {
                        __nv_bfloat162 h2 = __floats2bfloat162_rn(ox, oy);
                        *(__nv_bfloat162*)(base + reg * (2 * O) + j * 2) = h2;
                    } else {
                        *(float2*)(base + 4 * O + j * 4) = make_float2(ox, oy);
                    }
                }
            }
        }
    }
#undef LOAD_STAGE
#undef SMADDR
}

// ---------------- edge kernel: warp per edge, bf16x2 math --------------------
// q/k loaded as bf16x2 packs, z = (qa+qb)*(ka+kb) in bf16x2; softmax over
// 4-lane head groups; ctx scattered with red.global.add into g_acc.
template <int O>
__global__ __launch_bounds__(256) void edge_kernel(const int* __restrict__ esrc,
                                                   const int* __restrict__ edst, int E) {
    constexpr int CPT = O / 32;   // 4 or 2 channels per thread
    constexpr int NH2 = CPT / 2;  // bf16x2 regs: 2 or 1
    const float CEXP = ((O == 128) ? 0.25f : 0.3535533905932738f) * 1.44269504f;

    int gwarp = (blockIdx.x * blockDim.x + threadIdx.x) >> 5;
    int lane = threadIdx.x & 31;
    if (gwarp >= E) return;

    int s = esrc[gwarp];
    int d = edst[gwarp];
    int dd = abs(d - s);
    float ew = (dd > 8) ? 1.0f : ((dd == 8) ? 0.0f : -1.0f);

    const unsigned char* fa = g_featA + (size_t)d * (8 * O);
    const unsigned char* fb = g_featB + (size_t)s * (8 * O);
    int c = lane * CPT;

    __nv_bfloat162 qa2[NH2], ka2[NH2], qb2[NH2], kb2[NH2];
    float va[CPT], vb[CPT];
    if constexpr (NH2 == 2) {
        uint2 u;
        u = __ldg((const uint2*)(fa + c * 2));
        qa2[0] = *(__nv_bfloat162*)&u.x; qa2[1] = *(__nv_bfloat162*)&u.y;
        u = __ldg((const uint2*)(fa + 2 * O + c * 2));
        ka2[0] = *(__nv_bfloat162*)&u.x; ka2[1] = *(__nv_bfloat162*)&u.y;
        u = __ldg((const uint2*)(fb + c * 2));
        qb2[0] = *(__nv_bfloat162*)&u.x; qb2[1] = *(__nv_bfloat162*)&u.y;
        u = __ldg((const uint2*)(fb + 2 * O + c * 2));
        kb2[0] = *(__nv_bfloat162*)&u.x; kb2[1] = *(__nv_bfloat162*)&u.y;
        *(float4*)va = __ldg((const float4*)(fa + 4 * O + c * 4));
        *(float4*)vb = __ldg((const float4*)(fb + 4 * O + c * 4));
    } else {
        uint32_t u;
        u = __ldg((const uint32_t*)(fa + c * 2));
        qa2[0] = *(__nv_bfloat162*)&u;
        u = __ldg((const uint32_t*)(fa + 2 * O + c * 2));
        ka2[0] = *(__nv_bfloat162*)&u;
        u = __ldg((const uint32_t*)(fb + c * 2));
        qb2[0] = *(__nv_bfloat162*)&u;
        u = __ldg((const uint32_t*)(fb + 2 * O + c * 2));
        kb2[0] = *(__nv_bfloat162*)&u;
        *(float2*)va = __ldg((const float2*)(fa + 4 * O + c * 4));
        *(float2*)vb = __ldg((const float2*)(fb + 4 * O + c * 4));
    }

    float z[CPT];
#pragma unroll
    for (int h = 0; h < NH2; h++) {
        __nv_bfloat162 t = __hmul2(__hadd2(qa2[h], qb2[h]), __hadd2(ka2[h], kb2[h]));
        float2 f = __bfloat1622float2(t);
        z[2 * h] = f.x;
        z[2 * h + 1] = f.y;
    }
    float m = z[0];
#pragma unroll
    for (int i = 1; i < CPT; i++) m = fmaxf(m, z[i]);
    m = fmaxf(m, __shfl_xor_sync(0xFFFFFFFFu, m, 1));
    m = fmaxf(m, __shfl_xor_sync(0xFFFFFFFFu, m, 2));

    float p[CPT], sum = 0.0f;
#pragma unroll
    for (int i = 0; i < CPT; i++) {
        p[i] = ex2f((z[i] - m) * CEXP);
        sum += p[i];
    }
    sum += __shfl_xor_sync(0xFFFFFFFFu, sum, 1);
    sum += __shfl_xor_sync(0xFFFFFFFFu, sum, 2);
    float w = ew / sum;

    float ctx[CPT];
#pragma unroll
    for (int i = 0; i < CPT; i++) ctx[i] = p[i] * w * (va[i] + vb[i]);

    float* ap = g_acc + (size_t)d * O + c;
    if constexpr (CPT == 4) {
        asm volatile("red.global.add.v4.f32 [%0], {%1, %2, %3, %4};" ::"l"(ap),
                     "f"(ctx[0]), "f"(ctx[1]), "f"(ctx[2]), "f"(ctx[3])
                     : "memory");
    } else {
        asm volatile("red.global.add.v2.f32 [%0], {%1, %2};" ::"l"(ap), "f"(ctx[0]),
                     "f"(ctx[1])
                     : "memory");
    }
    if (lane == 0) atomicAdd(&g_cnt[d], 1.0f);
}

// ---------------- finalize: mean, (residual), relu; re-arms acc --------------
// mode 0: g_x0 = relu(acc/cnt); mode 1: g_h1 = relu(acc/cnt);
// mode 2: out = relu(acc/cnt + g_x0)
__global__ void finalize_kernel(float* __restrict__ outp, int O, int mode) {
    int idx = blockIdx.x * blockDim.x + threadIdx.x;
    int total = NN * O;
    if (idx >= total) return;
    int u = idx / O;
    float vv = g_acc[idx] / fmaxf(g_cnt[u], 1.0f);
    if (mode != 2) g_acc[idx] = 0.0f;  // re-arm accumulator for next layer
    if (mode == 2) vv += g_x0[idx];
    vv = fmaxf(vv, 0.0f);
    if (mode == 0)
        g_x0[idx] = vv;
    else if (mode == 1)
        g_h1[idx] = vv;
    else
        outp[idx] = vv;
}

// ---------------- launch -----------------------------------------------------
extern "C" void kernel_launch(void* const* d_in, const int* in_sizes, int n_in,
                              void* d_out, int out_size) {
    const float* x = (const float*)d_in[0];
    const int* e0 = (const int*)d_in[1];
    const int* e1 = (const int*)d_in[2];
    const int* e2 = (const int*)d_in[3];
    const float* wq0 = (const float*)d_in[5];
    const float* bq0 = (const float*)d_in[6];
    const float* wk0 = (const float*)d_in[7];
    const float* bk0 = (const float*)d_in[8];
    const float* wv0 = (const float*)d_in[9];
    const float* bv0 = (const float*)d_in[10];
    const float* wq1 = (const float*)d_in[11];
    const float* bq1 = (const float*)d_in[12];
    const float* wk1 = (const float*)d_in[13];
    const float* bk1 = (const float*)d_in[14];
    const float* wv1 = (const float*)d_in[15];
    const float* bv1 = (const float*)d_in[16];
    const float* wq2 = (const float*)d_in[17];
    const float* bq2 = (const float*)d_in[18];
    const float* wk2 = (const float*)d_in[19];
    const float* bk2 = (const float*)d_in[20];
    const float* wv2 = (const float*)d_in[21];
    const float* bv2 = (const float*)d_in[22];

    int E0 = in_sizes[1] / 2;
    int E1 = in_sizes[2] / 2;
    int E2 = in_sizes[3] / 2;

    int finGrid128 = (NN * 128 + 255) / 256;
    int finGrid64 = (NN * 64 + 255) / 256;
    int nblk = (NN + 127) / 128;
    int bw0 = (128 * 768 + 255) / 256;
    int bw1 = max((128 * 384 + 255) / 256, (NN + 255) / 256);
    int bw2 = max((64 * 768 + 255) / 256, (NN + 255) / 256);

    zero_acc<<<finGrid128, 256>>>(NN * 128);  // one-time; finalize re-arms after

    // ---- Layer 0: C=128, O=128 ----
    build_wcat<<<bw0, 256>>>(wq0, wk0, wv0, bq0, bk0, bv0, 128, 128);
    mma_gemm<128, 128><<<dim3(6, nblk), 256>>>(x, 0, NN);
    edge_kernel<128><<<(E0 + 7) / 8, 256>>>(e0, e0 + E0, E0);
    finalize_kernel<<<finGrid128, 256>>>(nullptr, 128, 0);

    // ---- Layer 1: C=128, O=64 ----
    build_wcat<<<bw1, 256>>>(wq1, wk1, wv1, bq1, bk1, bv1, 128, 64);
    mma_gemm<128, 64><<<dim3(3, nblk), 256>>>(nullptr, 1, NN);
    edge_kernel<64><<<(E1 + 7) / 8, 256>>>(e1, e1 + E1, E1);
    finalize_kernel<<<finGrid64, 256>>>(nullptr, 64, 1);

    // ---- Layer 2: C=64, O=128 ----
    build_wcat<<<bw2, 256>>>(wq2, wk2, wv2, bq2, bk2, bv2, 64, 128);
    mma_gemm<64, 128><<<dim3(6, nblk), 256>>>(nullptr, 2, NN);
    edge_kernel<128><<<(E2 + 7) / 8, 256>>>(e2, e2 + E2, E2);
    finalize_kernel<<<finGrid128, 256>>>((float*)d_out, 128, 2);
}

// round 8
// speedup vs baseline: 1.3439x; 1.0317x over previous
#include <cuda_runtime.h>
#include <cuda_bf16.h>
#include <math.h>
#include <stdint.h>

#define NN 50000

// ---------------- scratch (device globals; no allocations allowed) ----------
// Split per-node features. A = dst-side, B = src-side. Stride 8*O bytes:
//   [0   ,2O ) q  bf16[O]
//   [2O  ,4O ) k  bf16[O]
//   [4O  ,8O ) v  f32 [O]
__device__ __align__(16) unsigned char g_featA[NN * 1024];
__device__ __align__(16) unsigned char g_featB[NN * 1024];
__device__ float g_x0[NN * 128];      // relu(layer0 out), tf32-rounded
__device__ float g_h1[NN * 64];       // relu(layer1 out), tf32-rounded
__device__ float g_acc[NN * 128];     // edge-aggregation accumulator
__device__ float g_cnt[NN];           // edge count per dst
__device__ float g_wcatT[768 * 128];  // transposed transformed weights [M][K], tf32
__device__ float g_bcat[768];         // concatenated bias (bias only on A columns)

__device__ __forceinline__ float rna_tf32(float v) {
    float o;
    asm("cvt.rna.tf32.f32 %0, %1;" : "=f"(o) : "f"(v));
    return o;
}
__device__ __forceinline__ float ex2f(float v) {
    float o;
    asm("ex2.approx.f32 %0, %1;" : "=f"(o) : "f"(v));
    return o;
}

// ---------------- build W_catT[col][c] = rna([Wtop-Wbot | Wbot]); zero cnt ---
__global__ void build_wcat(const float* __restrict__ wq, const float* __restrict__ wk,
                           const float* __restrict__ wv, const float* __restrict__ bq,
                           const float* __restrict__ bk, const float* __restrict__ bv,
                           int C, int O) {
    int M = 6 * O;
    int idx = blockIdx.x * blockDim.x + threadIdx.x;
    if (idx < C * M) {
        int c = idx / M, col = idx % M;
        int grp = col / O, j = col % O;
        const float* w = (grp < 2) ? wq : (grp < 4 ? wk : wv);
        float top = w[c * O + j];
        float bot = w[(C + c) * O + j];
        float val = (grp & 1) ? bot : (top - bot);
        g_wcatT[(size_t)col * C + c] = rna_tf32(val);
    }
    if (idx < M) {
        int grp = idx / O, j = idx % O;
        const float* b = (grp < 2) ? bq : (grp < 4 ? bk : bv);
        g_bcat[idx] = (grp & 1) ? 0.0f : b[j];
    }
    if (idx < NN) g_cnt[idx] = 0.0f;  // prepare edge-count for this layer
}

// ---------------- one-time acc zero ------------------------------------------
__global__ void zero_acc(int n) {
    int idx = blockIdx.x * blockDim.x + threadIdx.x;
    if (idx < n) g_acc[idx] = 0.0f;
}

// ---------------- tf32 tensor-core GEMM --------------------------------------
// feat = A(NxK) @ g_wcatT^T + bias, written to split A/B node layout.
// srcsel: 0 -> Aext (layer-0 input x), 1 -> g_x0, 2 -> g_h1.
// ROUND: in-register rna of A fragments (only needed for external x).
template <int K, int O, bool ROUND>
__global__ __launch_bounds__(256, 2) void mma_gemm(const float* __restrict__ Aext,
                                                   int srcsel, int N) {
    const float* A = (srcsel == 0) ? Aext : ((srcsel == 1) ? g_x0 : g_h1);
    constexpr int PAD = 20;
    __shared__ float As[2][128 * PAD];
    __shared__ float Bs[2][128 * PAD];

    const int tid = threadIdx.x;
    const int lane = tid & 31;
    const int wid = tid >> 5;
    const int wm = (wid & 1) * 64;
    const int wn = (wid >> 1) * 32;
    const int bm = blockIdx.y * 128;
    const int bn = blockIdx.x * 128;

    float acc[4][4][4];
#pragma unroll
    for (int a = 0; a < 4; a++)
#pragma unroll
        for (int b = 0; b < 4; b++)
#pragma unroll
            for (int c = 0; c < 4; c++) acc[a][b][c] = 0.0f;

    const int r_ld = tid >> 1;
    const int ch0 = (tid & 1) * 2;
    const int garow = bm + r_ld;
    const float* aptr = A + (size_t)(garow < N ? garow : 0) * K;
    const int asz = (garow < N) ? 16 : 0;
    const float* bptr = g_wcatT + (size_t)(bn + r_ld) * K;

#define SMADDR(p) ((uint32_t)__cvta_generic_to_shared(p))

#define LOAD_STAGE(buf, k0)                                                          \
    {                                                                                \
        _Pragma("unroll") for (int i = 0; i < 2; i++) {                              \
            int ch = ch0 + i;                                                        \
            asm volatile("cp.async.cg.shared.global [%0], [%1], 16, %2;" ::"r"(      \
                             SMADDR(&As[buf][r_ld * PAD + ch * 4])),                 \
                         "l"(aptr + (k0) + ch * 4), "r"(asz));                       \
            asm volatile("cp.async.cg.shared.global [%0], [%1], 16;" ::"r"(          \
                             SMADDR(&Bs[buf][r_ld * PAD + ch * 4])),                 \
                         "l"(bptr + (k0) + ch * 4));                                 \
        }                                                                            \
        asm volatile("cp.async.commit_group;");                                      \
    }

    LOAD_STAGE(0, 0);
    constexpr int NIT = K / 16;
#pragma unroll
    for (int it = 0; it < NIT; it++) {
        const int buf = it & 1;
        if (it + 1 < NIT) {
            LOAD_STAGE(buf ^ 1, (it + 1) * 16);
            asm volatile("cp.async.wait_group 1;");
        } else {
            asm volatile("cp.async.wait_group 0;");
        }
        __syncthreads();

#pragma unroll
        for (int ks = 0; ks < 16; ks += 8) {
            uint32_t af[4][4];
#pragma unroll
            for (int mt = 0; mt < 4; mt++) {
                const float* p = &As[buf][(wm + mt * 16 + (lane & 15)) * PAD + ks +
                                          (lane >> 4) * 4];
                asm volatile(
                    "ldmatrix.sync.aligned.m8n8.x4.shared.b16 {%0,%1,%2,%3}, [%4];"
                    : "=r"(af[mt][0]), "=r"(af[mt][1]), "=r"(af[mt][2]), "=r"(af[mt][3])
                    : "r"(SMADDR(p)));
                if constexpr (ROUND) {
#pragma unroll
                    for (int r = 0; r < 4; r++)
                        af[mt][r] =
                            __float_as_uint(rna_tf32(__uint_as_float(af[mt][r])));
                }
            }
            uint32_t bf[2][4];
#pragma unroll
            for (int bi = 0; bi < 2; bi++) {
                const float* p = &Bs[buf][(wn + bi * 16 + (lane & 7) +
                                           ((lane >> 4) << 3)) *
                                              PAD +
                                          ks + ((lane >> 3) & 1) * 4];
                asm volatile(
                    "ldmatrix.sync.aligned.m8n8.x4.shared.b16 {%0,%1,%2,%3}, [%4];"
                    : "=r"(bf[bi][0]), "=r"(bf[bi][1]), "=r"(bf[bi][2]), "=r"(bf[bi][3])
                    : "r"(SMADDR(p)));
            }
#pragma unroll
            for (int mt = 0; mt < 4; mt++)
#pragma unroll
                for (int nt = 0; nt < 4; nt++) {
                    uint32_t b0 = bf[nt >> 1][(nt & 1) * 2];
                    uint32_t b1 = bf[nt >> 1][(nt & 1) * 2 + 1];
                    asm volatile(
                        "mma.sync.aligned.m16n8k8.row.col.f32.tf32.tf32.f32 "
                        "{%0,%1,%2,%3}, {%4,%5,%6,%7}, {%8,%9}, {%0,%1,%2,%3};"
                        : "+f"(acc[mt][nt][0]), "+f"(acc[mt][nt][1]),
                          "+f"(acc[mt][nt][2]), "+f"(acc[mt][nt][3])
                        : "r"(af[mt][0]), "r"(af[mt][1]), "r"(af[mt][2]),
                          "r"(af[mt][3]), "r"(b0), "r"(b1));
                }
        }
        __syncthreads();
    }

    // Epilogue: add bias, write split A/B mixed-precision layout.
#pragma unroll
    for (int mt = 0; mt < 4; mt++) {
        int r = bm + wm + mt * 16 + (lane >> 2);
#pragma unroll
        for (int half = 0; half < 2; half++) {
            int rr = r + half * 8;
            if (rr < N) {
                unsigned char* baseA = g_featA + (size_t)rr * (8 * O);
                unsigned char* baseB = g_featB + (size_t)rr * (8 * O);
#pragma unroll
                for (int nt = 0; nt < 4; nt++) {
                    int c = bn + wn + nt * 8 + (lane & 3) * 2;
                    int grp = c / O;
                    int j = c - grp * O;
                    float ox = acc[mt][nt][half * 2 + 0] + g_bcat[c];
                    float oy = acc[mt][nt][half * 2 + 1] + g_bcat[c + 1];
                    unsigned char* base = (grp & 1) ? baseB : baseA;
                    int reg = grp >> 1;  // 0=q, 1=k, 2=v
                    if (reg < 2) {
                        __nv_bfloat162 h2 = __floats2bfloat162_rn(ox, oy);
                        *(__nv_bfloat162*)(base + reg * (2 * O) + j * 2) = h2;
                    } else {
                        *(float2*)(base + 4 * O + j * 4) = make_float2(ox, oy);
                    }
                }
            }
        }
    }
#undef LOAD_STAGE
#undef SMADDR
}

// ---------------- edge kernel: TWO edges per warp, bf16x2 math ---------------
// 16 lanes per edge, CPT = O/16 channels per lane. Head = 2 lanes -> single
// xor-1 shuffle for max and for sum. red.global scatter into g_acc.
template <int O>
__global__ __launch_bounds__(256) void edge_kernel(const int* __restrict__ esrc,
                                                   const int* __restrict__ edst, int E) {
    constexpr int CPT = O / 16;   // 8 or 4 channels per lane
    constexpr int NH2 = CPT / 2;  // bf16x2 regs: 4 or 2
    const float CEXP = ((O == 128) ? 0.25f : 0.3535533905932738f) * 1.44269504f;

    int gwarp = (blockIdx.x * blockDim.x + threadIdx.x) >> 5;
    int lane = threadIdx.x & 31;
    int half = lane >> 4;  // which edge in the warp
    int sub = lane & 15;   // lane within edge
    int e = gwarp * 2 + half;
    bool valid = (e < E);
    int eidx = valid ? e : 0;

    int s = __ldg(&esrc[eidx]);
    int d = __ldg(&edst[eidx]);
    int dd = abs(d - s);
    float ew = (dd > 8) ? 1.0f : ((dd == 8) ? 0.0f : -1.0f);

    const unsigned char* fa = g_featA + (size_t)d * (8 * O);
    const unsigned char* fb = g_featB + (size_t)s * (8 * O);
    int c = sub * CPT;

    __nv_bfloat162 qa2[NH2], ka2[NH2], qb2[NH2], kb2[NH2];
    float va[CPT], vb[CPT];
    if constexpr (CPT == 8) {
        uint4 u;
        u = __ldg((const uint4*)(fa + c * 2));
        qa2[0] = *(__nv_bfloat162*)&u.x; qa2[1] = *(__nv_bfloat162*)&u.y;
        qa2[2] = *(__nv_bfloat162*)&u.z; qa2[3] = *(__nv_bfloat162*)&u.w;
        u = __ldg((const uint4*)(fa + 2 * O + c * 2));
        ka2[0] = *(__nv_bfloat162*)&u.x; ka2[1] = *(__nv_bfloat162*)&u.y;
        ka2[2] = *(__nv_bfloat162*)&u.z; ka2[3] = *(__nv_bfloat162*)&u.w;
        u = __ldg((const uint4*)(fb + c * 2));
        qb2[0] = *(__nv_bfloat162*)&u.x; qb2[1] = *(__nv_bfloat162*)&u.y;
        qb2[2] = *(__nv_bfloat162*)&u.z; qb2[3] = *(__nv_bfloat162*)&u.w;
        u = __ldg((const uint4*)(fb + 2 * O + c * 2));
        kb2[0] = *(__nv_bfloat162*)&u.x; kb2[1] = *(__nv_bfloat162*)&u.y;
        kb2[2] = *(__nv_bfloat162*)&u.z; kb2[3] = *(__nv_bfloat162*)&u.w;
        *(float4*)(va + 0) = __ldg((const float4*)(fa + 4 * O + c * 4));
        *(float4*)(va + 4) = __ldg((const float4*)(fa + 4 * O + c * 4 + 16));
        *(float4*)(vb + 0) = __ldg((const float4*)(fb + 4 * O + c * 4));
        *(float4*)(vb + 4) = __ldg((const float4*)(fb + 4 * O + c * 4 + 16));
    } else {
        uint2 u;
        u = __ldg((const uint2*)(fa + c * 2));
        qa2[0] = *(__nv_bfloat162*)&u.x; qa2[1] = *(__nv_bfloat162*)&u.y;
        u = __ldg((const uint2*)(fa + 2 * O + c * 2));
        ka2[0] = *(__nv_bfloat162*)&u.x; ka2[1] = *(__nv_bfloat162*)&u.y;
        u = __ldg((const uint2*)(fb + c * 2));
        qb2[0] = *(__nv_bfloat162*)&u.x; qb2[1] = *(__nv_bfloat162*)&u.y;
        u = __ldg((const uint2*)(fb + 2 * O + c * 2));
        kb2[0] = *(__nv_bfloat162*)&u.x; kb2[1] = *(__nv_bfloat162*)&u.y;
        *(float4*)va = __ldg((const float4*)(fa + 4 * O + c * 4));
        *(float4*)vb = __ldg((const float4*)(fb + 4 * O + c * 4));
    }

    float z[CPT];
#pragma unroll
    for (int h = 0; h < NH2; h++) {
        __nv_bfloat162 t = __hmul2(__hadd2(qa2[h], qb2[h]), __hadd2(ka2[h], kb2[h]));
        float2 f = __bfloat1622float2(t);
        z[2 * h] = f.x;
        z[2 * h + 1] = f.y;
    }
    // head = 2 lanes (2*CPT = hs channels): single xor-1 shuffle reductions
    float m = z[0];
#pragma unroll
    for (int i = 1; i < CPT; i++) m = fmaxf(m, z[i]);
    m = fmaxf(m, __shfl_xor_sync(0xFFFFFFFFu, m, 1));

    float p[CPT], sum = 0.0f;
#pragma unroll
    for (int i = 0; i < CPT; i++) {
        p[i] = ex2f((z[i] - m) * CEXP);
        sum += p[i];
    }
    sum += __shfl_xor_sync(0xFFFFFFFFu, sum, 1);
    float w = ew / sum;

    float ctx[CPT];
#pragma unroll
    for (int i = 0; i < CPT; i++) ctx[i] = p[i] * w * (va[i] + vb[i]);

    if (valid) {
        float* ap = g_acc + (size_t)d * O + c;
        if constexpr (CPT == 8) {
            asm volatile("red.global.add.v4.f32 [%0], {%1, %2, %3, %4};" ::"l"(ap),
                         "f"(ctx[0]), "f"(ctx[1]), "f"(ctx[2]), "f"(ctx[3])
                         : "memory");
            asm volatile("red.global.add.v4.f32 [%0], {%1, %2, %3, %4};" ::"l"(ap + 4),
                         "f"(ctx[4]), "f"(ctx[5]), "f"(ctx[6]), "f"(ctx[7])
                         : "memory");
        } else {
            asm volatile("red.global.add.v4.f32 [%0], {%1, %2, %3, %4};" ::"l"(ap),
                         "f"(ctx[0]), "f"(ctx[1]), "f"(ctx[2]), "f"(ctx[3])
                         : "memory");
        }
        if (sub == 0) atomicAdd(&g_cnt[d], 1.0f);
    }
}

// ---------------- finalize: mean, (residual), relu; re-arms acc --------------
// mode 0: g_x0 = rna(relu(acc/cnt)); mode 1: g_h1 = rna(relu(acc/cnt));
// mode 2: out = relu(acc/cnt + g_x0)
__global__ void finalize_kernel(float* __restrict__ outp, int O, int mode) {
    int idx = blockIdx.x * blockDim.x + threadIdx.x;
    int total = NN * O;
    if (idx >= total) return;
    int u = idx / O;
    float vv = g_acc[idx] / fmaxf(g_cnt[u], 1.0f);
    if (mode != 2) g_acc[idx] = 0.0f;  // re-arm accumulator for next layer
    if (mode == 2) vv += g_x0[idx];
    vv = fmaxf(vv, 0.0f);
    if (mode == 0)
        g_x0[idx] = rna_tf32(vv);
    else if (mode == 1)
        g_h1[idx] = rna_tf32(vv);
    else
        outp[idx] = vv;
}

// ---------------- launch -----------------------------------------------------
extern "C" void kernel_launch(void* const* d_in, const int* in_sizes, int n_in,
                              void* d_out, int out_size) {
    const float* x = (const float*)d_in[0];
    const int* e0 = (const int*)d_in[1];
    const int* e1 = (const int*)d_in[2];
    const int* e2 = (const int*)d_in[3];
    const float* wq0 = (const float*)d_in[5];
    const float* bq0 = (const float*)d_in[6];
    const float* wk0 = (const float*)d_in[7];
    const float* bk0 = (const float*)d_in[8];
    const float* wv0 = (const float*)d_in[9];
    const float* bv0 = (const float*)d_in[10];
    const float* wq1 = (const float*)d_in[11];
    const float* bq1 = (const float*)d_in[12];
    const float* wk1 = (const float*)d_in[13];
    const float* bk1 = (const float*)d_in[14];
    const float* wv1 = (const float*)d_in[15];
    const float* bv1 = (const float*)d_in[16];
    const float* wq2 = (const float*)d_in[17];
    const float* bq2 = (const float*)d_in[18];
    const float* wk2 = (const float*)d_in[19];
    const float* bk2 = (const float*)d_in[20];
    const float* wv2 = (const float*)d_in[21];
    const float* bv2 = (const float*)d_in[22];

    int E0 = in_sizes[1] / 2;
    int E1 = in_sizes[2] / 2;
    int E2 = in_sizes[3] / 2;

    int finGrid128 = (NN * 128 + 255) / 256;
    int finGrid64 = (NN * 64 + 255) / 256;
    int nblk = (NN + 127) / 128;
    int bw0 = (128 * 768 + 255) / 256;
    int bw1 = max((128 * 384 + 255) / 256, (NN + 255) / 256);
    int bw2 = max((64 * 768 + 255) / 256, (NN + 255) / 256);
    // edge grids: 2 edges per warp, 8 warps per block
    int eg0 = ((E0 + 1) / 2 + 7) / 8;
    int eg1 = ((E1 + 1) / 2 + 7) / 8;
    int eg2 = ((E2 + 1) / 2 + 7) / 8;

    zero_acc<<<finGrid128, 256>>>(NN * 128);  // one-time; finalize re-arms after

    // ---- Layer 0: C=128, O=128 ----
    build_wcat<<<bw0, 256>>>(wq0, wk0, wv0, bq0, bk0, bv0, 128, 128);
    mma_gemm<128, 128, true><<<dim3(6, nblk), 256>>>(x, 0, NN);
    edge_kernel<128><<<eg0, 256>>>(e0, e0 + E0, E0);
    finalize_kernel<<<finGrid128, 256>>>(nullptr, 128, 0);

    // ---- Layer 1: C=128, O=64 ----
    build_wcat<<<bw1, 256>>>(wq1, wk1, wv1, bq1, bk1, bv1, 128, 64);
    mma_gemm<128, 64, false><<<dim3(3, nblk), 256>>>(nullptr, 1, NN);
    edge_kernel<64><<<eg1, 256>>>(e1, e1 + E1, E1);
    finalize_kernel<<<finGrid64, 256>>>(nullptr, 64, 1);

    // ---- Layer 2: C=64, O=128 ----
    build_wcat<<<bw2, 256>>>(wq2, wk2, wv2, bq2, bk2, bv2, 64, 128);
    mma_gemm<64, 128, false><<<dim3(6, nblk), 256>>>(nullptr, 2, NN);
    edge_kernel<128><<<eg2, 256>>>(e2, e2 + E2, E2);
    finalize_kernel<<<finGrid128, 256>>>((float*)d_out, 128, 2);
}

// round 10
// speedup vs baseline: 1.3688x; 1.0186x over previous
#include <cuda_runtime.h>
#include <cuda_bf16.h>
#include <math.h>
#include <stdint.h>

#define NN 50000

// ---------------- scratch (device globals; no allocations allowed) ----------
// Split per-node features. A = dst-side, B = src-side. Stride 8*O bytes:
//   [0   ,2O ) q  bf16[O]
//   [2O  ,4O ) k  bf16[O]
//   [4O  ,8O ) v  f32 [O]
__device__ __align__(16) unsigned char g_featA[NN * 1024];
__device__ __align__(16) unsigned char g_featB[NN * 1024];
__device__ float g_x0[NN * 128];      // relu(layer0 out), tf32-rounded
__device__ float g_h1[NN * 64];       // relu(layer1 out), tf32-rounded
__device__ float g_acc[NN * 128];     // edge-aggregation accumulator
__device__ float g_cnt[NN];           // edge count per dst
__device__ float g_wcatT[768 * 128];  // transposed transformed weights [M][K], tf32
__device__ float g_bcat[768];         // concatenated bias (bias only on A columns)

__device__ __forceinline__ float rna_tf32(float v) {
    float o;
    asm("cvt.rna.tf32.f32 %0, %1;" : "=f"(o) : "f"(v));
    return o;
}
__device__ __forceinline__ float ex2f(float v) {
    float o;
    asm("ex2.approx.f32 %0, %1;" : "=f"(o) : "f"(v));
    return o;
}

// ---------------- build W_catT[col][c] = rna([Wtop-Wbot | Wbot]); zero cnt ---
__global__ void build_wcat(const float* __restrict__ wq, const float* __restrict__ wk,
                           const float* __restrict__ wv, const float* __restrict__ bq,
                           const float* __restrict__ bk, const float* __restrict__ bv,
                           int C, int O) {
    int M = 6 * O;
    int idx = blockIdx.x * blockDim.x + threadIdx.x;
    if (idx < C * M) {
        int c = idx / M, col = idx % M;
        int grp = col / O, j = col % O;
        const float* w = (grp < 2) ? wq : (grp < 4 ? wk : wv);
        float top = w[c * O + j];
        float bot = w[(C + c) * O + j];
        float val = (grp & 1) ? bot : (top - bot);
        g_wcatT[(size_t)col * C + c] = rna_tf32(val);
    }
    if (idx < M) {
        int grp = idx / O, j = idx % O;
        const float* b = (grp < 2) ? bq : (grp < 4 ? bk : bv);
        g_bcat[idx] = (grp & 1) ? 0.0f : b[j];
    }
    if (idx < NN) g_cnt[idx] = 0.0f;  // prepare edge-count for this layer
}

// ---------------- one-time acc zero (vectorized) -----------------------------
__global__ void zero_acc(int n4) {
    int idx = blockIdx.x * blockDim.x + threadIdx.x;
    if (idx < n4) ((float4*)g_acc)[idx] = make_float4(0.f, 0.f, 0.f, 0.f);
}

// ---------------- tf32 tensor-core GEMM --------------------------------------
// feat = A(NxK) @ g_wcatT^T + bias, written to split A/B node layout.
// srcsel: 0 -> Aext (layer-0 input x), 1 -> g_x0, 2 -> g_h1.
// ROUND: in-register rna of A fragments (only needed for external x).
template <int K, int O, bool ROUND>
__global__ __launch_bounds__(256, 2) void mma_gemm(const float* __restrict__ Aext,
                                                   int srcsel, int N) {
    const float* A = (srcsel == 0) ? Aext : ((srcsel == 1) ? g_x0 : g_h1);
    constexpr int PAD = 20;
    __shared__ float As[2][128 * PAD];
    __shared__ float Bs[2][128 * PAD];

    const int tid = threadIdx.x;
    const int lane = tid & 31;
    const int wid = tid >> 5;
    const int wm = (wid & 1) * 64;
    const int wn = (wid >> 1) * 32;
    const int bm = blockIdx.y * 128;
    const int bn = blockIdx.x * 128;

    float acc[4][4][4];
#pragma unroll
    for (int a = 0; a < 4; a++)
#pragma unroll
        for (int b = 0; b < 4; b++)
#pragma unroll
            for (int c = 0; c < 4; c++) acc[a][b][c] = 0.0f;

    const int r_ld = tid >> 1;
    const int ch0 = (tid & 1) * 2;
    const int garow = bm + r_ld;
    const float* aptr = A + (size_t)(garow < N ? garow : 0) * K;
    const int asz = (garow < N) ? 16 : 0;
    const float* bptr = g_wcatT + (size_t)(bn + r_ld) * K;

#define SMADDR(p) ((uint32_t)__cvta_generic_to_shared(p))

#define LOAD_STAGE(buf, k0)                                                          \
    {                                                                                \
        _Pragma("unroll") for (int i = 0; i < 2; i++) {                              \
            int ch = ch0 + i;                                                        \
            asm volatile("cp.async.cg.shared.global [%0], [%1], 16, %2;" ::"r"(      \
                             SMADDR(&As[buf][r_ld * PAD + ch * 4])),                 \
                         "l"(aptr + (k0) + ch * 4), "r"(asz));                       \
            asm volatile("cp.async.cg.shared.global [%0], [%1], 16;" ::"r"(          \
                             SMADDR(&Bs[buf][r_ld * PAD + ch * 4])),                 \
                         "l"(bptr + (k0) + ch * 4));                                 \
        }                                                                            \
        asm volatile("cp.async.commit_group;");                                      \
    }

    LOAD_STAGE(0, 0);
    constexpr int NIT = K / 16;
#pragma unroll
    for (int it = 0; it < NIT; it++) {
        const int buf = it & 1;
        if (it + 1 < NIT) {
            LOAD_STAGE(buf ^ 1, (it + 1) * 16);
            asm volatile("cp.async.wait_group 1;");
        } else {
            asm volatile("cp.async.wait_group 0;");
        }
        __syncthreads();

#pragma unroll
        for (int ks = 0; ks < 16; ks += 8) {
            uint32_t af[4][4];
#pragma unroll
            for (int mt = 0; mt < 4; mt++) {
                const float* p = &As[buf][(wm + mt * 16 + (lane & 15)) * PAD + ks +
                                          (lane >> 4) * 4];
                asm volatile(
                    "ldmatrix.sync.aligned.m8n8.x4.shared.b16 {%0,%1,%2,%3}, [%4];"
                    : "=r"(af[mt][0]), "=r"(af[mt][1]), "=r"(af[mt][2]), "=r"(af[mt][3])
                    : "r"(SMADDR(p)));
                if constexpr (ROUND) {
#pragma unroll
                    for (int r = 0; r < 4; r++)
                        af[mt][r] =
                            __float_as_uint(rna_tf32(__uint_as_float(af[mt][r])));
                }
            }
            uint32_t bf[2][4];
#pragma unroll
            for (int bi = 0; bi < 2; bi++) {
                const float* p = &Bs[buf][(wn + bi * 16 + (lane & 7) +
                                           ((lane >> 4) << 3)) *
                                              PAD +
                                          ks + ((lane >> 3) & 1) * 4];
                asm volatile(
                    "ldmatrix.sync.aligned.m8n8.x4.shared.b16 {%0,%1,%2,%3}, [%4];"
                    : "=r"(bf[bi][0]), "=r"(bf[bi][1]), "=r"(bf[bi][2]), "=r"(bf[bi][3])
                    : "r"(SMADDR(p)));
            }
#pragma unroll
            for (int mt = 0; mt < 4; mt++)
#pragma unroll
                for (int nt = 0; nt < 4; nt++) {
                    uint32_t b0 = bf[nt >> 1][(nt & 1) * 2];
                    uint32_t b1 = bf[nt >> 1][(nt & 1) * 2 + 1];
                    asm volatile(
                        "mma.sync.aligned.m16n8k8.row.col.f32.tf32.tf32.f32 "
                        "{%0,%1,%2,%3}, {%4,%5,%6,%7}, {%8,%9}, {%0,%1,%2,%3};"
                        : "+f"(acc[mt][nt][0]), "+f"(acc[mt][nt][1]),
                          "+f"(acc[mt][nt][2]), "+f"(acc[mt][nt][3])
                        : "r"(af[mt][0]), "r"(af[mt][1]), "r"(af[mt][2]),
                          "r"(af[mt][3]), "r"(b0), "r"(b1));
                }
        }
        __syncthreads();
    }

    // Epilogue: add bias, write split A/B mixed-precision layout.
#pragma unroll
    for (int mt = 0; mt < 4; mt++) {
        int r = bm + wm + mt * 16 + (lane >> 2);
#pragma unroll
        for (int half = 0; half < 2; half++) {
            int rr = r + half * 8;
            if (rr < N) {
                unsigned char* baseA = g_featA + (size_t)rr * (8 * O);
                unsigned char* baseB = g_featB + (size_t)rr * (8 * O);
#pragma unroll
                for (int nt = 0; nt < 4; nt++) {
                    int c = bn + wn + nt * 8 + (lane & 3) * 2;
                    int grp = c / O;
                    int j = c - grp * O;
                    float ox = acc[mt][nt][half * 2 + 0] + g_bcat[c];
                    float oy = acc[mt][nt][half * 2 + 1] + g_bcat[c + 1];
                    unsigned char* base = (grp & 1) ? baseB : baseA;
                    int reg = grp >> 1;  // 0=q, 1=k, 2=v
                    if (reg < 2) {
                        __nv_bfloat162 h2 = __floats2bfloat162_rn(ox, oy);
                        *(__nv_bfloat162*)(base + reg * (2 * O) + j * 2) = h2;
                    } else {
                        *(float2*)(base + 4 * O + j * 4) = make_float2(ox, oy);
                    }
                }
            }
        }
    }
#undef LOAD_STAGE
#undef SMADDR
}

// ---------------- edge kernel, O=128: ONE edge per warp ----------------------
// CPT=4 channels/lane, head = 4 lanes (xor1 + xor2 shuffles). q/k bf16, v f32.
__global__ __launch_bounds__(256) void edge_kernel128(const int* __restrict__ esrc,
                                                      const int* __restrict__ edst,
                                                      int E) {
    constexpr int O = 128;
    const float CEXP = 0.25f * 1.44269504f;

    int gwarp = (blockIdx.x * blockDim.x + threadIdx.x) >> 5;
    int lane = threadIdx.x & 31;
    if (gwarp >= E) return;

    int s = esrc[gwarp];
    int d = edst[gwarp];
    int dd = abs(d - s);
    float ew = (dd > 8) ? 1.0f : ((dd == 8) ? 0.0f : -1.0f);

    const unsigned char* fa = g_featA + (size_t)d * (8 * O);
    const unsigned char* fb = g_featB + (size_t)s * (8 * O);
    int c = lane * 4;

    __nv_bfloat162 qa2[2], ka2[2], qb2[2], kb2[2];
    float va[4], vb[4];
    uint2 u;
    u = __ldg((const uint2*)(fa + c * 2));
    qa2[0] = *(__nv_bfloat162*)&u.x; qa2[1] = *(__nv_bfloat162*)&u.y;
    u = __ldg((const uint2*)(fa + 2 * O + c * 2));
    ka2[0] = *(__nv_bfloat162*)&u.x; ka2[1] = *(__nv_bfloat162*)&u.y;
    u = __ldg((const uint2*)(fb + c * 2));
    qb2[0] = *(__nv_bfloat162*)&u.x; qb2[1] = *(__nv_bfloat162*)&u.y;
    u = __ldg((const uint2*)(fb + 2 * O + c * 2));
    kb2[0] = *(__nv_bfloat162*)&u.x; kb2[1] = *(__nv_bfloat162*)&u.y;
    *(float4*)va = __ldg((const float4*)(fa + 4 * O + c * 4));
    *(float4*)vb = __ldg((const float4*)(fb + 4 * O + c * 4));

    float z[4];
#pragma unroll
    for (int h = 0; h < 2; h++) {
        __nv_bfloat162 t = __hmul2(__hadd2(qa2[h], qb2[h]), __hadd2(ka2[h], kb2[h]));
        float2 f = __bfloat1622float2(t);
        z[2 * h] = f.x;
        z[2 * h + 1] = f.y;
    }
    float m = fmaxf(fmaxf(z[0], z[1]), fmaxf(z[2], z[3]));
    m = fmaxf(m, __shfl_xor_sync(0xFFFFFFFFu, m, 1));
    m = fmaxf(m, __shfl_xor_sync(0xFFFFFFFFu, m, 2));

    float p[4], sum = 0.0f;
#pragma unroll
    for (int i = 0; i < 4; i++) {
        p[i] = ex2f((z[i] - m) * CEXP);
        sum += p[i];
    }
    sum += __shfl_xor_sync(0xFFFFFFFFu, sum, 1);
    sum += __shfl_xor_sync(0xFFFFFFFFu, sum, 2);
    float w = ew / sum;

    float ctx[4];
#pragma unroll
    for (int i = 0; i < 4; i++) ctx[i] = p[i] * w * (va[i] + vb[i]);

    float* ap = g_acc + (size_t)d * O + c;
    asm volatile("red.global.add.v4.f32 [%0], {%1, %2, %3, %4};" ::"l"(ap),
                 "f"(ctx[0]), "f"(ctx[1]), "f"(ctx[2]), "f"(ctx[3])
                 : "memory");
    if (lane == 0) atomicAdd(&g_cnt[d], 1.0f);
}

// ---------------- edge kernel, O=64: TWO edges per warp ----------------------
// 16 lanes/edge, CPT=4, head = 2 lanes (single xor1 shuffle). q/k bf16, v f32.
__global__ __launch_bounds__(256) void edge_kernel64(const int* __restrict__ esrc,
                                                     const int* __restrict__ edst,
                                                     int E) {
    constexpr int O = 64;
    const float CEXP = 0.3535533905932738f * 1.44269504f;

    int gwarp = (blockIdx.x * blockDim.x + threadIdx.x) >> 5;
    int lane = threadIdx.x & 31;
    int half = lane >> 4;
    int sub = lane & 15;
    int e = gwarp * 2 + half;
    bool valid = (e < E);
    int eidx = valid ? e : 0;

    int s = __ldg(&esrc[eidx]);
    int d = __ldg(&edst[eidx]);
    int dd = abs(d - s);
    float ew = (dd > 8) ? 1.0f : ((dd == 8) ? 0.0f : -1.0f);

    const unsigned char* fa = g_featA + (size_t)d * (8 * O);
    const unsigned char* fb = g_featB + (size_t)s * (8 * O);
    int c = sub * 4;

    __nv_bfloat162 qa2[2], ka2[2], qb2[2], kb2[2];
    float va[4], vb[4];
    uint2 u;
    u = __ldg((const uint2*)(fa + c * 2));
    qa2[0] = *(__nv_bfloat162*)&u.x; qa2[1] = *(__nv_bfloat162*)&u.y;
    u = __ldg((const uint2*)(fa + 2 * O + c * 2));
    ka2[0] = *(__nv_bfloat162*)&u.x; ka2[1] = *(__nv_bfloat162*)&u.y;
    u = __ldg((const uint2*)(fb + c * 2));
    qb2[0] = *(__nv_bfloat162*)&u.x; qb2[1] = *(__nv_bfloat162*)&u.y;
    u = __ldg((const uint2*)(fb + 2 * O + c * 2));
    kb2[0] = *(__nv_bfloat162*)&u.x; kb2[1] = *(__nv_bfloat162*)&u.y;
    *(float4*)va = __ldg((const float4*)(fa + 4 * O + c * 4));
    *(float4*)vb = __ldg((const float4*)(fb + 4 * O + c * 4));

    float z[4];
#pragma unroll
    for (int h = 0; h < 2; h++) {
        __nv_bfloat162 t = __hmul2(__hadd2(qa2[h], qb2[h]), __hadd2(ka2[h], kb2[h]));
        float2 f = __bfloat1622float2(t);
        z[2 * h] = f.x;
        z[2 * h + 1] = f.y;
    }
    float m = fmaxf(fmaxf(z[0], z[1]), fmaxf(z[2], z[3]));
    m = fmaxf(m, __shfl_xor_sync(0xFFFFFFFFu, m, 1));

    float p[4], sum = 0.0f;
#pragma unroll
    for (int i = 0; i < 4; i++) {
        p[i] = ex2f((z[i] - m) * CEXP);
        sum += p[i];
    }
    sum += __shfl_xor_sync(0xFFFFFFFFu, sum, 1);
    float w = ew / sum;

    float ctx[4];
#pragma unroll
    for (int i = 0; i < 4; i++) ctx[i] = p[i] * w * (va[i] + vb[i]);

    if (valid) {
        float* ap = g_acc + (size_t)d * O + c;
        asm volatile("red.global.add.v4.f32 [%0], {%1, %2, %3, %4};" ::"l"(ap),
                     "f"(ctx[0]), "f"(ctx[1]), "f"(ctx[2]), "f"(ctx[3])
                     : "memory");
        if (sub == 0) atomicAdd(&g_cnt[d], 1.0f);
    }
}

// ---------------- finalize (float4 per thread): mean/residual/relu -----------
// mode 0: g_x0 = rna(relu(acc/cnt)); mode 1: g_h1 = rna(relu(acc/cnt));
// mode 2: out = relu(acc/cnt + g_x0). Re-arms acc for modes 0/1.
__global__ void finalize_kernel(float* __restrict__ outp, int O, int mode) {
    int idx = blockIdx.x * blockDim.x + threadIdx.x;  // float4 index
    int total4 = NN * O / 4;
    if (idx >= total4) return;
    int u = idx / (O / 4);
    float inv = 1.0f / fmaxf(g_cnt[u], 1.0f);
    float4 a = ((float4*)g_acc)[idx];
    if (mode != 2) ((float4*)g_acc)[idx] = make_float4(0.f, 0.f, 0.f, 0.f);
    float vv[4] = {a.x * inv, a.y * inv, a.z * inv, a.w * inv};
    if (mode == 2) {
        float4 r = ((const float4*)g_x0)[idx];
        float4 o;
        o.x = fmaxf(vv[0] + r.x, 0.0f);
        o.y = fmaxf(vv[1] + r.y, 0.0f);
        o.z = fmaxf(vv[2] + r.z, 0.0f);
        o.w = fmaxf(vv[3] + r.w, 0.0f);
        ((float4*)outp)[idx] = o;
    } else {
        float4 o;
        o.x = rna_tf32(fmaxf(vv[0], 0.0f));
        o.y = rna_tf32(fmaxf(vv[1], 0.0f));
        o.z = rna_tf32(fmaxf(vv[2], 0.0f));
        o.w = rna_tf32(fmaxf(vv[3], 0.0f));
        if (mode == 0)
            ((float4*)g_x0)[idx] = o;
        else
            ((float4*)g_h1)[idx] = o;
    }
}

// ---------------- launch -----------------------------------------------------
extern "C" void kernel_launch(void* const* d_in, const int* in_sizes, int n_in,
                              void* d_out, int out_size) {
    const float* x = (const float*)d_in[0];
    const int* e0 = (const int*)d_in[1];
    const int* e1 = (const int*)d_in[2];
    const int* e2 = (const int*)d_in[3];
    const float* wq0 = (const float*)d_in[5];
    const float* bq0 = (const float*)d_in[6];
    const float* wk0 = (const float*)d_in[7];
    const float* bk0 = (const float*)d_in[8];
    const float* wv0 = (const float*)d_in[9];
    const float* bv0 = (const float*)d_in[10];
    const float* wq1 = (const float*)d_in[11];
    const float* bq1 = (const float*)d_in[12];
    const float* wk1 = (const float*)d_in[13];
    const float* bk1 = (const float*)d_in[14];
    const float* wv1 = (const float*)d_in[15];
    const float* bv1 = (const float*)d_in[16];
    const float* wq2 = (const float*)d_in[17];
    const float* bq2 = (const float*)d_in[18];
    const float* wk2 = (const float*)d_in[19];
    const float* bk2 = (const float*)d_in[20];
    const float* wv2 = (const float*)d_in[21];
    const float* bv2 = (const float*)d_in[22];

    int E0 = in_sizes[1] / 2;
    int E1 = in_sizes[2] / 2;
    int E2 = in_sizes[3] / 2;

    int fin4_128 = (NN * 128 / 4 + 255) / 256;
    int fin4_64 = (NN * 64 / 4 + 255) / 256;
    int nblk = (NN + 127) / 128;
    int bw0 = (128 * 768 + 255) / 256;
    int bw1 = max((128 * 384 + 255) / 256, (NN + 255) / 256);
    int bw2 = max((64 * 768 + 255) / 256, (NN + 255) / 256);

    zero_acc<<<fin4_128, 256>>>(NN * 128 / 4);  // one-time; finalize re-arms after

    // ---- Layer 0: C=128, O=128 ----
    build_wcat<<<bw0, 256>>>(wq0, wk0, wv0, bq0, bk0, bv0, 128, 128);
    mma_gemm<128, 128, true><<<dim3(6, nblk), 256>>>(x, 0, NN);
    edge_kernel128<<<(E0 + 7) / 8, 256>>>(e0, e0 + E0, E0);
    finalize_kernel<<<fin4_128, 256>>>(nullptr, 128, 0);

    // ---- Layer 1: C=128, O=64 ----
    build_wcat<<<bw1, 256>>>(wq1, wk1, wv1, bq1, bk1, bv1, 128, 64);
    mma_gemm<128, 64, false><<<dim3(3, nblk), 256>>>(nullptr, 1, NN);
    edge_kernel64<<<((E1 + 1) / 2 + 7) / 8, 256>>>(e1, e1 + E1, E1);
    finalize_kernel<<<fin4_64, 256>>>(nullptr, 64, 1);

    // ---- Layer 2: C=64, O=128 ----
    build_wcat<<<bw2, 256>>>(wq2, wk2, wv2, bq2, bk2, bv2, 64, 128);
    mma_gemm<64, 128, false><<<dim3(6, nblk), 256>>>(nullptr, 2, NN);
    edge_kernel128<<<(E2 + 7) / 8, 256>>>(e2, e2 + E2, E2);
    finalize_kernel<<<fin4_128, 256>>>((float*)d_out, 128, 2);
}

// round 11
// speedup vs baseline: 1.4236x; 1.0400x over previous
#include <cuda_runtime.h>
#include <cuda_bf16.h>
#include <cuda_fp16.h>
#include <math.h>
#include <stdint.h>

#define NN 50000

// ---------------- scratch (device globals; no allocations allowed) ----------
// Split per-node features. A = dst-side, B = src-side. Stride 6*O bytes:
//   [0   ,2O ) q  bf16[O]
//   [2O  ,4O ) k  bf16[O]
//   [4O  ,6O ) v  fp16[O]
__device__ __align__(16) unsigned char g_featA[NN * 768];
__device__ __align__(16) unsigned char g_featB[NN * 768];
__device__ float g_x0[NN * 128];      // relu(layer0 out), tf32-rounded
__device__ float g_h1[NN * 64];       // relu(layer1 out), tf32-rounded
__device__ float g_acc[NN * 128];     // edge-aggregation accumulator (f32)
__device__ float g_cnt[NN];           // edge count per dst
__device__ float g_wcatT[768 * 128];  // transposed transformed weights [M][K], tf32
__device__ float g_bcat[768];         // concatenated bias (bias only on A columns)

__device__ __forceinline__ float rna_tf32(float v) {
    float o;
    asm("cvt.rna.tf32.f32 %0, %1;" : "=f"(o) : "f"(v));
    return o;
}
__device__ __forceinline__ float ex2f(float v) {
    float o;
    asm("ex2.approx.f32 %0, %1;" : "=f"(o) : "f"(v));
    return o;
}

// ---------------- build W_catT[col][c] = rna([Wtop-Wbot | Wbot]); zero cnt ---
__global__ void build_wcat(const float* __restrict__ wq, const float* __restrict__ wk,
                           const float* __restrict__ wv, const float* __restrict__ bq,
                           const float* __restrict__ bk, const float* __restrict__ bv,
                           int C, int O) {
    int M = 6 * O;
    int idx = blockIdx.x * blockDim.x + threadIdx.x;
    if (idx < C * M) {
        int c = idx / M, col = idx % M;
        int grp = col / O, j = col % O;
        const float* w = (grp < 2) ? wq : (grp < 4 ? wk : wv);
        float top = w[c * O + j];
        float bot = w[(C + c) * O + j];
        float val = (grp & 1) ? bot : (top - bot);
        g_wcatT[(size_t)col * C + c] = rna_tf32(val);
    }
    if (idx < M) {
        int grp = idx / O, j = idx % O;
        const float* b = (grp < 2) ? bq : (grp < 4 ? bk : bv);
        g_bcat[idx] = (grp & 1) ? 0.0f : b[j];
    }
    if (idx < NN) g_cnt[idx] = 0.0f;  // prepare edge-count for this layer
}

// ---------------- one-time acc zero (vectorized) -----------------------------
__global__ void zero_acc(int n4) {
    int idx = blockIdx.x * blockDim.x + threadIdx.x;
    if (idx < n4) ((float4*)g_acc)[idx] = make_float4(0.f, 0.f, 0.f, 0.f);
}

// ---------------- tf32 tensor-core GEMM --------------------------------------
// feat = A(NxK) @ g_wcatT^T + bias, written to split A/B node layout
// (q/k bf16, v fp16). srcsel: 0 -> Aext, 1 -> g_x0, 2 -> g_h1.
// ROUND: in-register rna of A fragments (only needed for external x).
template <int K, int O, bool ROUND>
__global__ __launch_bounds__(256, 2) void mma_gemm(const float* __restrict__ Aext,
                                                   int srcsel, int N) {
    const float* A = (srcsel == 0) ? Aext : ((srcsel == 1) ? g_x0 : g_h1);
    constexpr int PAD = 20;
    __shared__ float As[2][128 * PAD];
    __shared__ float Bs[2][128 * PAD];

    const int tid = threadIdx.x;
    const int lane = tid & 31;
    const int wid = tid >> 5;
    const int wm = (wid & 1) * 64;
    const int wn = (wid >> 1) * 32;
    const int bm = blockIdx.y * 128;
    const int bn = blockIdx.x * 128;

    float acc[4][4][4];
#pragma unroll
    for (int a = 0; a < 4; a++)
#pragma unroll
        for (int b = 0; b < 4; b++)
#pragma unroll
            for (int c = 0; c < 4; c++) acc[a][b][c] = 0.0f;

    const int r_ld = tid >> 1;
    const int ch0 = (tid & 1) * 2;
    const int garow = bm + r_ld;
    const float* aptr = A + (size_t)(garow < N ? garow : 0) * K;
    const int asz = (garow < N) ? 16 : 0;
    const float* bptr = g_wcatT + (size_t)(bn + r_ld) * K;

#define SMADDR(p) ((uint32_t)__cvta_generic_to_shared(p))

#define LOAD_STAGE(buf, k0)                                                          \
    {                                                                                \
        _Pragma("unroll") for (int i = 0; i < 2; i++) {                              \
            int ch = ch0 + i;                                                        \
            asm volatile("cp.async.cg.shared.global [%0], [%1], 16, %2;" ::"r"(      \
                             SMADDR(&As[buf][r_ld * PAD + ch * 4])),                 \
                         "l"(aptr + (k0) + ch * 4), "r"(asz));                       \
            asm volatile("cp.async.cg.shared.global [%0], [%1], 16;" ::"r"(          \
                             SMADDR(&Bs[buf][r_ld * PAD + ch * 4])),                 \
                         "l"(bptr + (k0) + ch * 4));                                 \
        }                                                                            \
        asm volatile("cp.async.commit_group;");                                      \
    }

    LOAD_STAGE(0, 0);
    constexpr int NIT = K / 16;
#pragma unroll
    for (int it = 0; it < NIT; it++) {
        const int buf = it & 1;
        if (it + 1 < NIT) {
            LOAD_STAGE(buf ^ 1, (it + 1) * 16);
            asm volatile("cp.async.wait_group 1;");
        } else {
            asm volatile("cp.async.wait_group 0;");
        }
        __syncthreads();

#pragma unroll
        for (int ks = 0; ks < 16; ks += 8) {
            uint32_t af[4][4];
#pragma unroll
            for (int mt = 0; mt < 4; mt++) {
                const float* p = &As[buf][(wm + mt * 16 + (lane & 15)) * PAD + ks +
                                          (lane >> 4) * 4];
                asm volatile(
                    "ldmatrix.sync.aligned.m8n8.x4.shared.b16 {%0,%1,%2,%3}, [%4];"
                    : "=r"(af[mt][0]), "=r"(af[mt][1]), "=r"(af[mt][2]), "=r"(af[mt][3])
                    : "r"(SMADDR(p)));
                if constexpr (ROUND) {
#pragma unroll
                    for (int r = 0; r < 4; r++)
                        af[mt][r] =
                            __float_as_uint(rna_tf32(__uint_as_float(af[mt][r])));
                }
            }
            uint32_t bf[2][4];
#pragma unroll
            for (int bi = 0; bi < 2; bi++) {
                const float* p = &Bs[buf][(wn + bi * 16 + (lane & 7) +
                                           ((lane >> 4) << 3)) *
                                              PAD +
                                          ks + ((lane >> 3) & 1) * 4];
                asm volatile(
                    "ldmatrix.sync.aligned.m8n8.x4.shared.b16 {%0,%1,%2,%3}, [%4];"
                    : "=r"(bf[bi][0]), "=r"(bf[bi][1]), "=r"(bf[bi][2]), "=r"(bf[bi][3])
                    : "r"(SMADDR(p)));
            }
#pragma unroll
            for (int mt = 0; mt < 4; mt++)
#pragma unroll
                for (int nt = 0; nt < 4; nt++) {
                    uint32_t b0 = bf[nt >> 1][(nt & 1) * 2];
                    uint32_t b1 = bf[nt >> 1][(nt & 1) * 2 + 1];
                    asm volatile(
                        "mma.sync.aligned.m16n8k8.row.col.f32.tf32.tf32.f32 "
                        "{%0,%1,%2,%3}, {%4,%5,%6,%7}, {%8,%9}, {%0,%1,%2,%3};"
                        : "+f"(acc[mt][nt][0]), "+f"(acc[mt][nt][1]),
                          "+f"(acc[mt][nt][2]), "+f"(acc[mt][nt][3])
                        : "r"(af[mt][0]), "r"(af[mt][1]), "r"(af[mt][2]),
                          "r"(af[mt][3]), "r"(b0), "r"(b1));
                }
        }
        __syncthreads();
    }

    // Epilogue: add bias, write split A/B layout (q/k bf16, v fp16; stride 6*O).
#pragma unroll
    for (int mt = 0; mt < 4; mt++) {
        int r = bm + wm + mt * 16 + (lane >> 2);
#pragma unroll
        for (int half = 0; half < 2; half++) {
            int rr = r + half * 8;
            if (rr < N) {
                unsigned char* baseA = g_featA + (size_t)rr * (6 * O);
                unsigned char* baseB = g_featB + (size_t)rr * (6 * O);
#pragma unroll
                for (int nt = 0; nt < 4; nt++) {
                    int c = bn + wn + nt * 8 + (lane & 3) * 2;
                    int grp = c / O;
                    int j = c - grp * O;
                    float ox = acc[mt][nt][half * 2 + 0] + g_bcat[c];
                    float oy = acc[mt][nt][half * 2 + 1] + g_bcat[c + 1];
                    unsigned char* base = (grp & 1) ? baseB : baseA;
                    int reg = grp >> 1;  // 0=q, 1=k, 2=v
                    if (reg < 2) {
                        __nv_bfloat162 h2 = __floats2bfloat162_rn(ox, oy);
                        *(__nv_bfloat162*)(base + reg * (2 * O) + j * 2) = h2;
                    } else {
                        __half2 h2 = __floats2half2_rn(ox, oy);
                        *(__half2*)(base + 4 * O + j * 2) = h2;
                    }
                }
            }
        }
    }
#undef LOAD_STAGE
#undef SMADDR
}

// ---------------- edge kernel, O=128: ONE edge per warp ----------------------
// CPT=4 channels/lane. q/k bf16, v fp16; all per-lane loads are 8B uint2.
__global__ __launch_bounds__(256) void edge_kernel128(const int* __restrict__ esrc,
                                                      const int* __restrict__ edst,
                                                      int E) {
    constexpr int O = 128;
    const float CEXP = 0.25f * 1.44269504f;

    int gwarp = (blockIdx.x * blockDim.x + threadIdx.x) >> 5;
    int lane = threadIdx.x & 31;
    if (gwarp >= E) return;

    int s = esrc[gwarp];
    int d = edst[gwarp];
    int dd = abs(d - s);
    float ew = (dd > 8) ? 1.0f : ((dd == 8) ? 0.0f : -1.0f);

    const unsigned char* fa = g_featA + (size_t)d * (6 * O);
    const unsigned char* fb = g_featB + (size_t)s * (6 * O);
    int c = lane * 4;

    __nv_bfloat162 qa2[2], ka2[2], qb2[2], kb2[2];
    __half2 va2[2], vb2[2];
    uint2 u;
    u = __ldg((const uint2*)(fa + c * 2));
    qa2[0] = *(__nv_bfloat162*)&u.x; qa2[1] = *(__nv_bfloat162*)&u.y;
    u = __ldg((const uint2*)(fa + 2 * O + c * 2));
    ka2[0] = *(__nv_bfloat162*)&u.x; ka2[1] = *(__nv_bfloat162*)&u.y;
    u = __ldg((const uint2*)(fa + 4 * O + c * 2));
    va2[0] = *(__half2*)&u.x; va2[1] = *(__half2*)&u.y;
    u = __ldg((const uint2*)(fb + c * 2));
    qb2[0] = *(__nv_bfloat162*)&u.x; qb2[1] = *(__nv_bfloat162*)&u.y;
    u = __ldg((const uint2*)(fb + 2 * O + c * 2));
    kb2[0] = *(__nv_bfloat162*)&u.x; kb2[1] = *(__nv_bfloat162*)&u.y;
    u = __ldg((const uint2*)(fb + 4 * O + c * 2));
    vb2[0] = *(__half2*)&u.x; vb2[1] = *(__half2*)&u.y;

    float z[4], vsum[4];
#pragma unroll
    for (int h = 0; h < 2; h++) {
        __nv_bfloat162 t = __hmul2(__hadd2(qa2[h], qb2[h]), __hadd2(ka2[h], kb2[h]));
        float2 f = __bfloat1622float2(t);
        z[2 * h] = f.x;
        z[2 * h + 1] = f.y;
        float2 fa2 = __half22float2(va2[h]);
        float2 fb2 = __half22float2(vb2[h]);
        vsum[2 * h] = fa2.x + fb2.x;
        vsum[2 * h + 1] = fa2.y + fb2.y;
    }
    float m = fmaxf(fmaxf(z[0], z[1]), fmaxf(z[2], z[3]));
    m = fmaxf(m, __shfl_xor_sync(0xFFFFFFFFu, m, 1));
    m = fmaxf(m, __shfl_xor_sync(0xFFFFFFFFu, m, 2));

    float p[4], sum = 0.0f;
#pragma unroll
    for (int i = 0; i < 4; i++) {
        p[i] = ex2f((z[i] - m) * CEXP);
        sum += p[i];
    }
    sum += __shfl_xor_sync(0xFFFFFFFFu, sum, 1);
    sum += __shfl_xor_sync(0xFFFFFFFFu, sum, 2);
    float w = ew / sum;

    float ctx[4];
#pragma unroll
    for (int i = 0; i < 4; i++) ctx[i] = p[i] * w * vsum[i];

    float* ap = g_acc + (size_t)d * O + c;
    asm volatile("red.global.add.v4.f32 [%0], {%1, %2, %3, %4};" ::"l"(ap),
                 "f"(ctx[0]), "f"(ctx[1]), "f"(ctx[2]), "f"(ctx[3])
                 : "memory");
    if (lane == 0) atomicAdd(&g_cnt[d], 1.0f);
}

// ---------------- edge kernel, O=64: TWO edges per warp ----------------------
// 16 lanes/edge, CPT=4, head = 2 lanes. q/k bf16, v fp16.
__global__ __launch_bounds__(256) void edge_kernel64(const int* __restrict__ esrc,
                                                     const int* __restrict__ edst,
                                                     int E) {
    constexpr int O = 64;
    const float CEXP = 0.3535533905932738f * 1.44269504f;

    int gwarp = (blockIdx.x * blockDim.x + threadIdx.x) >> 5;
    int lane = threadIdx.x & 31;
    int half = lane >> 4;
    int sub = lane & 15;
    int e = gwarp * 2 + half;
    bool valid = (e < E);
    int eidx = valid ? e : 0;

    int s = __ldg(&esrc[eidx]);
    int d = __ldg(&edst[eidx]);
    int dd = abs(d - s);
    float ew = (dd > 8) ? 1.0f : ((dd == 8) ? 0.0f : -1.0f);

    const unsigned char* fa = g_featA + (size_t)d * (6 * O);
    const unsigned char* fb = g_featB + (size_t)s * (6 * O);
    int c = sub * 4;

    __nv_bfloat162 qa2[2], ka2[2], qb2[2], kb2[2];
    __half2 va2[2], vb2[2];
    uint2 u;
    u = __ldg((const uint2*)(fa + c * 2));
    qa2[0] = *(__nv_bfloat162*)&u.x; qa2[1] = *(__nv_bfloat162*)&u.y;
    u = __ldg((const uint2*)(fa + 2 * O + c * 2));
    ka2[0] = *(__nv_bfloat162*)&u.x; ka2[1] = *(__nv_bfloat162*)&u.y;
    u = __ldg((const uint2*)(fa + 4 * O + c * 2));
    va2[0] = *(__half2*)&u.x; va2[1] = *(__half2*)&u.y;
    u = __ldg((const uint2*)(fb + c * 2));
    qb2[0] = *(__nv_bfloat162*)&u.x; qb2[1] = *(__nv_bfloat162*)&u.y;
    u = __ldg((const uint2*)(fb + 2 * O + c * 2));
    kb2[0] = *(__nv_bfloat162*)&u.x; kb2[1] = *(__nv_bfloat162*)&u.y;
    u = __ldg((const uint2*)(fb + 4 * O + c * 2));
    vb2[0] = *(__half2*)&u.x; vb2[1] = *(__half2*)&u.y;

    float z[4], vsum[4];
#pragma unroll
    for (int h = 0; h < 2; h++) {
        __nv_bfloat162 t = __hmul2(__hadd2(qa2[h], qb2[h]), __hadd2(ka2[h], kb2[h]));
        float2 f = __bfloat1622float2(t);
        z[2 * h] = f.x;
        z[2 * h + 1] = f.y;
        float2 fa2 = __half22float2(va2[h]);
        float2 fb2 = __half22float2(vb2[h]);
        vsum[2 * h] = fa2.x + fb2.x;
        vsum[2 * h + 1] = fa2.y + fb2.y;
    }
    float m = fmaxf(fmaxf(z[0], z[1]), fmaxf(z[2], z[3]));
    m = fmaxf(m, __shfl_xor_sync(0xFFFFFFFFu, m, 1));

    float p[4], sum = 0.0f;
#pragma unroll
    for (int i = 0; i < 4; i++) {
        p[i] = ex2f((z[i] - m) * CEXP);
        sum += p[i];
    }
    sum += __shfl_xor_sync(0xFFFFFFFFu, sum, 1);
    float w = ew / sum;

    float ctx[4];
#pragma unroll
    for (int i = 0; i < 4; i++) ctx[i] = p[i] * w * vsum[i];

    if (valid) {
        float* ap = g_acc + (size_t)d * O + c;
        asm volatile("red.global.add.v4.f32 [%0], {%1, %2, %3, %4};" ::"l"(ap),
                     "f"(ctx[0]), "f"(ctx[1]), "f"(ctx[2]), "f"(ctx[3])
                     : "memory");
        if (sub == 0) atomicAdd(&g_cnt[d], 1.0f);
    }
}

// ---------------- finalize (float4 per thread): mean/residual/relu -----------
// mode 0: g_x0 = rna(relu(acc/cnt)); mode 1: g_h1 = rna(relu(acc/cnt));
// mode 2: out = relu(acc/cnt + g_x0). Re-arms acc for modes 0/1.
__global__ void finalize_kernel(float* __restrict__ outp, int O, int mode) {
    int idx = blockIdx.x * blockDim.x + threadIdx.x;  // float4 index
    int total4 = NN * O / 4;
    if (idx >= total4) return;
    int u = idx / (O / 4);
    float inv = 1.0f / fmaxf(g_cnt[u], 1.0f);
    float4 a = ((float4*)g_acc)[idx];
    if (mode != 2) ((float4*)g_acc)[idx] = make_float4(0.f, 0.f, 0.f, 0.f);
    float vv[4] = {a.x * inv, a.y * inv, a.z * inv, a.w * inv};
    if (mode == 2) {
        float4 r = ((const float4*)g_x0)[idx];
        float4 o;
        o.x = fmaxf(vv[0] + r.x, 0.0f);
        o.y = fmaxf(vv[1] + r.y, 0.0f);
        o.z = fmaxf(vv[2] + r.z, 0.0f);
        o.w = fmaxf(vv[3] + r.w, 0.0f);
        ((float4*)outp)[idx] = o;
    } else {
        float4 o;
        o.x = rna_tf32(fmaxf(vv[0], 0.0f));
        o.y = rna_tf32(fmaxf(vv[1], 0.0f));
        o.z = rna_tf32(fmaxf(vv[2], 0.0f));
        o.w = rna_tf32(fmaxf(vv[3], 0.0f));
        if (mode == 0)
            ((float4*)g_x0)[idx] = o;
        else
            ((float4*)g_h1)[idx] = o;
    }
}

// ---------------- launch -----------------------------------------------------
extern "C" void kernel_launch(void* const* d_in, const int* in_sizes, int n_in,
                              void* d_out, int out_size) {
    const float* x = (const float*)d_in[0];
    const int* e0 = (const int*)d_in[1];
    const int* e1 = (const int*)d_in[2];
    const int* e2 = (const int*)d_in[3];
    const float* wq0 = (const float*)d_in[5];
    const float* bq0 = (const float*)d_in[6];
    const float* wk0 = (const float*)d_in[7];
    const float* bk0 = (const float*)d_in[8];
    const float* wv0 = (const float*)d_in[9];
    const float* bv0 = (const float*)d_in[10];
    const float* wq1 = (const float*)d_in[11];
    const float* bq1 = (const float*)d_in[12];
    const float* wk1 = (const float*)d_in[13];
    const float* bk1 = (const float*)d_in[14];
    const float* wv1 = (const float*)d_in[15];
    const float* bv1 = (const float*)d_in[16];
    const float* wq2 = (const float*)d_in[17];
    const float* bq2 = (const float*)d_in[18];
    const float* wk2 = (const float*)d_in[19];
    const float* bk2 = (const float*)d_in[20];
    const float* wv2 = (const float*)d_in[21];
    const float* bv2 = (const float*)d_in[22];

    int E0 = in_sizes[1] / 2;
    int E1 = in_sizes[2] / 2;
    int E2 = in_sizes[3] / 2;

    int fin4_128 = (NN * 128 / 4 + 255) / 256;
    int fin4_64 = (NN * 64 / 4 + 255) / 256;
    int nblk = (NN + 127) / 128;
    int bw0 = (128 * 768 + 255) / 256;
    int bw1 = max((128 * 384 + 255) / 256, (NN + 255) / 256);
    int bw2 = max((64 * 768 + 255) / 256, (NN + 255) / 256);

    zero_acc<<<fin4_128, 256>>>(NN * 128 / 4);  // one-time; finalize re-arms after

    // ---- Layer 0: C=128, O=128 ----
    build_wcat<<<bw0, 256>>>(wq0, wk0, wv0, bq0, bk0, bv0, 128, 128);
    mma_gemm<128, 128, true><<<dim3(6, nblk), 256>>>(x, 0, NN);
    edge_kernel128<<<(E0 + 7) / 8, 256>>>(e0, e0 + E0, E0);
    finalize_kernel<<<fin4_128, 256>>>(nullptr, 128, 0);

    // ---- Layer 1: C=128, O=64 ----
    build_wcat<<<bw1, 256>>>(wq1, wk1, wv1, bq1, bk1, bv1, 128, 64);
    mma_gemm<128, 64, false><<<dim3(3, nblk), 256>>>(nullptr, 1, NN);
    edge_kernel64<<<((E1 + 1) / 2 + 7) / 8, 256>>>(e1, e1 + E1, E1);
    finalize_kernel<<<fin4_64, 256>>>(nullptr, 64, 1);

    // ---- Layer 2: C=64, O=128 ----
    build_wcat<<<bw2, 256>>>(wq2, wk2, wv2, bq2, bk2, bv2, 64, 128);
    mma_gemm<64, 128, false><<<dim3(6, nblk), 256>>>(nullptr, 2, NN);
    edge_kernel128<<<(E2 + 7) / 8, 256>>>(e2, e2 + E2, E2);
    finalize_kernel<<<fin4_128, 256>>>((float*)d_out, 128, 2);
}

// round 12
// speedup vs baseline: 1.4718x; 1.0338x over previous
#include <cuda_runtime.h>
#include <cuda_bf16.h>
#include <cuda_fp16.h>
#include <math.h>
#include <stdint.h>

#define NN 50000

// ---------------- scratch (device globals; no allocations allowed) ----------
// Split per-node features. A = dst-side, B = src-side. Stride 6*O bytes:
//   [0   ,2O ) q  bf16[O]
//   [2O  ,4O ) k  bf16[O]
//   [4O  ,6O ) v  fp16[O]
__device__ __align__(16) unsigned char g_featA[NN * 768];
__device__ __align__(16) unsigned char g_featB[NN * 768];
__device__ float g_x0[NN * 128];      // relu(layer0 out), tf32-rounded
__device__ float g_h1[NN * 64];       // relu(layer1 out), tf32-rounded
__device__ float g_acc[NN * 128];     // edge-aggregation accumulator (f32)
__device__ float g_cnt[NN];           // edge count per dst
__device__ float g_wcatT[768 * 128];  // transposed transformed weights [M][K], tf32
__device__ float g_bcat[768];         // concatenated bias (bias only on A columns)

__device__ __forceinline__ float rna_tf32(float v) {
    float o;
    asm("cvt.rna.tf32.f32 %0, %1;" : "=f"(o) : "f"(v));
    return o;
}
__device__ __forceinline__ float ex2f(float v) {
    float o;
    asm("ex2.approx.f32 %0, %1;" : "=f"(o) : "f"(v));
    return o;
}
__device__ __forceinline__ float rcpf(float v) {
    float o;
    asm("rcp.approx.f32 %0, %1;" : "=f"(o) : "f"(v));
    return o;
}

// ---------------- build W_catT[col][c] = rna([Wtop-Wbot | Wbot]); zero cnt ---
__global__ void build_wcat(const float* __restrict__ wq, const float* __restrict__ wk,
                           const float* __restrict__ wv, const float* __restrict__ bq,
                           const float* __restrict__ bk, const float* __restrict__ bv,
                           int C, int O) {
    int M = 6 * O;
    int idx = blockIdx.x * blockDim.x + threadIdx.x;
    if (idx < C * M) {
        int c = idx / M, col = idx % M;
        int grp = col / O, j = col % O;
        const float* w = (grp < 2) ? wq : (grp < 4 ? wk : wv);
        float top = w[c * O + j];
        float bot = w[(C + c) * O + j];
        float val = (grp & 1) ? bot : (top - bot);
        g_wcatT[(size_t)col * C + c] = rna_tf32(val);
    }
    if (idx < M) {
        int grp = idx / O, j = idx % O;
        const float* b = (grp < 2) ? bq : (grp < 4 ? bk : bv);
        g_bcat[idx] = (grp & 1) ? 0.0f : b[j];
    }
    if (idx < NN) g_cnt[idx] = 0.0f;  // prepare edge-count for this layer
}

// ---------------- one-time acc zero (vectorized) -----------------------------
__global__ void zero_acc(int n4) {
    int idx = blockIdx.x * blockDim.x + threadIdx.x;
    if (idx < n4) ((float4*)g_acc)[idx] = make_float4(0.f, 0.f, 0.f, 0.f);
}

// ---------------- tf32 tensor-core GEMM --------------------------------------
// feat = A(NxK) @ g_wcatT^T + bias, written to split A/B node layout
// (q/k bf16, v fp16). srcsel: 0 -> Aext, 1 -> g_x0, 2 -> g_h1.
// ROUND: in-register rna of A fragments (only needed for external x).
template <int K, int O, bool ROUND>
__global__ __launch_bounds__(256, 2) void mma_gemm(const float* __restrict__ Aext,
                                                   int srcsel, int N) {
    const float* A = (srcsel == 0) ? Aext : ((srcsel == 1) ? g_x0 : g_h1);
    constexpr int PAD = 20;
    __shared__ float As[2][128 * PAD];
    __shared__ float Bs[2][128 * PAD];

    const int tid = threadIdx.x;
    const int lane = tid & 31;
    const int wid = tid >> 5;
    const int wm = (wid & 1) * 64;
    const int wn = (wid >> 1) * 32;
    const int bm = blockIdx.y * 128;
    const int bn = blockIdx.x * 128;

    float acc[4][4][4];
#pragma unroll
    for (int a = 0; a < 4; a++)
#pragma unroll
        for (int b = 0; b < 4; b++)
#pragma unroll
            for (int c = 0; c < 4; c++) acc[a][b][c] = 0.0f;

    const int r_ld = tid >> 1;
    const int ch0 = (tid & 1) * 2;
    const int garow = bm + r_ld;
    const float* aptr = A + (size_t)(garow < N ? garow : 0) * K;
    const int asz = (garow < N) ? 16 : 0;
    const float* bptr = g_wcatT + (size_t)(bn + r_ld) * K;

#define SMADDR(p) ((uint32_t)__cvta_generic_to_shared(p))

#define LOAD_STAGE(buf, k0)                                                          \
    {                                                                                \
        _Pragma("unroll") for (int i = 0; i < 2; i++) {                              \
            int ch = ch0 + i;                                                        \
            asm volatile("cp.async.cg.shared.global [%0], [%1], 16, %2;" ::"r"(      \
                             SMADDR(&As[buf][r_ld * PAD + ch * 4])),                 \
                         "l"(aptr + (k0) + ch * 4), "r"(asz));                       \
            asm volatile("cp.async.cg.shared.global [%0], [%1], 16;" ::"r"(          \
                             SMADDR(&Bs[buf][r_ld * PAD + ch * 4])),                 \
                         "l"(bptr + (k0) + ch * 4));                                 \
        }                                                                            \
        asm volatile("cp.async.commit_group;");                                      \
    }

    LOAD_STAGE(0, 0);
    constexpr int NIT = K / 16;
#pragma unroll
    for (int it = 0; it < NIT; it++) {
        const int buf = it & 1;
        if (it + 1 < NIT) {
            LOAD_STAGE(buf ^ 1, (it + 1) * 16);
            asm volatile("cp.async.wait_group 1;");
        } else {
            asm volatile("cp.async.wait_group 0;");
        }
        __syncthreads();

#pragma unroll
        for (int ks = 0; ks < 16; ks += 8) {
            uint32_t af[4][4];
#pragma unroll
            for (int mt = 0; mt < 4; mt++) {
                const float* p = &As[buf][(wm + mt * 16 + (lane & 15)) * PAD + ks +
                                          (lane >> 4) * 4];
                asm volatile(
                    "ldmatrix.sync.aligned.m8n8.x4.shared.b16 {%0,%1,%2,%3}, [%4];"
                    : "=r"(af[mt][0]), "=r"(af[mt][1]), "=r"(af[mt][2]), "=r"(af[mt][3])
                    : "r"(SMADDR(p)));
                if constexpr (ROUND) {
#pragma unroll
                    for (int r = 0; r < 4; r++)
                        af[mt][r] =
                            __float_as_uint(rna_tf32(__uint_as_float(af[mt][r])));
                }
            }
            uint32_t bf[2][4];
#pragma unroll
            for (int bi = 0; bi < 2; bi++) {
                const float* p = &Bs[buf][(wn + bi * 16 + (lane & 7) +
                                           ((lane >> 4) << 3)) *
                                              PAD +
                                          ks + ((lane >> 3) & 1) * 4];
                asm volatile(
                    "ldmatrix.sync.aligned.m8n8.x4.shared.b16 {%0,%1,%2,%3}, [%4];"
                    : "=r"(bf[bi][0]), "=r"(bf[bi][1]), "=r"(bf[bi][2]), "=r"(bf[bi][3])
                    : "r"(SMADDR(p)));
            }
#pragma unroll
            for (int mt = 0; mt < 4; mt++)
#pragma unroll
                for (int nt = 0; nt < 4; nt++) {
                    uint32_t b0 = bf[nt >> 1][(nt & 1) * 2];
                    uint32_t b1 = bf[nt >> 1][(nt & 1) * 2 + 1];
                    asm volatile(
                        "mma.sync.aligned.m16n8k8.row.col.f32.tf32.tf32.f32 "
                        "{%0,%1,%2,%3}, {%4,%5,%6,%7}, {%8,%9}, {%0,%1,%2,%3};"
                        : "+f"(acc[mt][nt][0]), "+f"(acc[mt][nt][1]),
                          "+f"(acc[mt][nt][2]), "+f"(acc[mt][nt][3])
                        : "r"(af[mt][0]), "r"(af[mt][1]), "r"(af[mt][2]),
                          "r"(af[mt][3]), "r"(b0), "r"(b1));
                }
        }
        __syncthreads();
    }

    // Epilogue: add bias, write split A/B layout (q/k bf16, v fp16; stride 6*O).
#pragma unroll
    for (int mt = 0; mt < 4; mt++) {
        int r = bm + wm + mt * 16 + (lane >> 2);
#pragma unroll
        for (int half = 0; half < 2; half++) {
            int rr = r + half * 8;
            if (rr < N) {
                unsigned char* baseA = g_featA + (size_t)rr * (6 * O);
                unsigned char* baseB = g_featB + (size_t)rr * (6 * O);
#pragma unroll
                for (int nt = 0; nt < 4; nt++) {
                    int c = bn + wn + nt * 8 + (lane & 3) * 2;
                    int grp = c / O;
                    int j = c - grp * O;
                    float ox = acc[mt][nt][half * 2 + 0] + g_bcat[c];
                    float oy = acc[mt][nt][half * 2 + 1] + g_bcat[c + 1];
                    unsigned char* base = (grp & 1) ? baseB : baseA;
                    int reg = grp >> 1;  // 0=q, 1=k, 2=v
                    if (reg < 2) {
                        __nv_bfloat162 h2 = __floats2bfloat162_rn(ox, oy);
                        *(__nv_bfloat162*)(base + reg * (2 * O) + j * 2) = h2;
                    } else {
                        __half2 h2 = __floats2half2_rn(ox, oy);
                        *(__half2*)(base + 4 * O + j * 2) = h2;
                    }
                }
            }
        }
    }
#undef LOAD_STAGE
#undef SMADDR
}

// ---------------- edge kernel, O=128: ONE edge per warp ----------------------
// CPT=4 channels/lane. q/k bf16, v fp16. No max-subtraction (|z| small),
// rcp.approx for the softmax denominator.
__global__ __launch_bounds__(256) void edge_kernel128(const int* __restrict__ esrc,
                                                      const int* __restrict__ edst,
                                                      int E) {
    constexpr int O = 128;
    const float CEXP = 0.25f * 1.44269504f;

    int gwarp = (blockIdx.x * blockDim.x + threadIdx.x) >> 5;
    int lane = threadIdx.x & 31;
    if (gwarp >= E) return;

    int s = esrc[gwarp];
    int d = edst[gwarp];
    int dd = abs(d - s);
    float ew = (dd > 8) ? 1.0f : ((dd == 8) ? 0.0f : -1.0f);

    const unsigned char* fa = g_featA + (size_t)d * (6 * O);
    const unsigned char* fb = g_featB + (size_t)s * (6 * O);
    int c = lane * 4;

    __nv_bfloat162 qa2[2], ka2[2], qb2[2], kb2[2];
    __half2 va2[2], vb2[2];
    uint2 u;
    u = __ldg((const uint2*)(fa + c * 2));
    qa2[0] = *(__nv_bfloat162*)&u.x; qa2[1] = *(__nv_bfloat162*)&u.y;
    u = __ldg((const uint2*)(fa + 2 * O + c * 2));
    ka2[0] = *(__nv_bfloat162*)&u.x; ka2[1] = *(__nv_bfloat162*)&u.y;
    u = __ldg((const uint2*)(fa + 4 * O + c * 2));
    va2[0] = *(__half2*)&u.x; va2[1] = *(__half2*)&u.y;
    u = __ldg((const uint2*)(fb + c * 2));
    qb2[0] = *(__nv_bfloat162*)&u.x; qb2[1] = *(__nv_bfloat162*)&u.y;
    u = __ldg((const uint2*)(fb + 2 * O + c * 2));
    kb2[0] = *(__nv_bfloat162*)&u.x; kb2[1] = *(__nv_bfloat162*)&u.y;
    u = __ldg((const uint2*)(fb + 4 * O + c * 2));
    vb2[0] = *(__half2*)&u.x; vb2[1] = *(__half2*)&u.y;

    float p[4], vsum[4], sum = 0.0f;
#pragma unroll
    for (int h = 0; h < 2; h++) {
        __nv_bfloat162 t = __hmul2(__hadd2(qa2[h], qb2[h]), __hadd2(ka2[h], kb2[h]));
        float2 f = __bfloat1622float2(t);
        p[2 * h] = ex2f(f.x * CEXP);
        p[2 * h + 1] = ex2f(f.y * CEXP);
        sum += p[2 * h] + p[2 * h + 1];
        float2 fa2 = __half22float2(va2[h]);
        float2 fb2 = __half22float2(vb2[h]);
        vsum[2 * h] = fa2.x + fb2.x;
        vsum[2 * h + 1] = fa2.y + fb2.y;
    }
    sum += __shfl_xor_sync(0xFFFFFFFFu, sum, 1);
    sum += __shfl_xor_sync(0xFFFFFFFFu, sum, 2);
    float w = ew * rcpf(sum);

    float ctx[4];
#pragma unroll
    for (int i = 0; i < 4; i++) ctx[i] = p[i] * w * vsum[i];

    float* ap = g_acc + (size_t)d * O + c;
    asm volatile("red.global.add.v4.f32 [%0], {%1, %2, %3, %4};" ::"l"(ap),
                 "f"(ctx[0]), "f"(ctx[1]), "f"(ctx[2]), "f"(ctx[3])
                 : "memory");
    if (lane == 0) atomicAdd(&g_cnt[d], 1.0f);
}

// ---------------- edge kernel, O=64: TWO edges per warp ----------------------
// 16 lanes/edge, CPT=4, head = 2 lanes. No max-subtraction; rcp.approx.
__global__ __launch_bounds__(256) void edge_kernel64(const int* __restrict__ esrc,
                                                     const int* __restrict__ edst,
                                                     int E) {
    constexpr int O = 64;
    const float CEXP = 0.3535533905932738f * 1.44269504f;

    int gwarp = (blockIdx.x * blockDim.x + threadIdx.x) >> 5;
    int lane = threadIdx.x & 31;
    int half = lane >> 4;
    int sub = lane & 15;
    int e = gwarp * 2 + half;
    bool valid = (e < E);
    int eidx = valid ? e : 0;

    int s = __ldg(&esrc[eidx]);
    int d = __ldg(&edst[eidx]);
    int dd = abs(d - s);
    float ew = (dd > 8) ? 1.0f : ((dd == 8) ? 0.0f : -1.0f);

    const unsigned char* fa = g_featA + (size_t)d * (6 * O);
    const unsigned char* fb = g_featB + (size_t)s * (6 * O);
    int c = sub * 4;

    __nv_bfloat162 qa2[2], ka2[2], qb2[2], kb2[2];
    __half2 va2[2], vb2[2];
    uint2 u;
    u = __ldg((const uint2*)(fa + c * 2));
    qa2[0] = *(__nv_bfloat162*)&u.x; qa2[1] = *(__nv_bfloat162*)&u.y;
    u = __ldg((const uint2*)(fa + 2 * O + c * 2));
    ka2[0] = *(__nv_bfloat162*)&u.x; ka2[1] = *(__nv_bfloat162*)&u.y;
    u = __ldg((const uint2*)(fa + 4 * O + c * 2));
    va2[0] = *(__half2*)&u.x; va2[1] = *(__half2*)&u.y;
    u = __ldg((const uint2*)(fb + c * 2));
    qb2[0] = *(__nv_bfloat162*)&u.x; qb2[1] = *(__nv_bfloat162*)&u.y;
    u = __ldg((const uint2*)(fb + 2 * O + c * 2));
    kb2[0] = *(__nv_bfloat162*)&u.x; kb2[1] = *(__nv_bfloat162*)&u.y;
    u = __ldg((const uint2*)(fb + 4 * O + c * 2));
    vb2[0] = *(__half2*)&u.x; vb2[1] = *(__half2*)&u.y;

    float p[4], vsum[4], sum = 0.0f;
#pragma unroll
    for (int h = 0; h < 2; h++) {
        __nv_bfloat162 t = __hmul2(__hadd2(qa2[h], qb2[h]), __hadd2(ka2[h], kb2[h]));
        float2 f = __bfloat1622float2(t);
        p[2 * h] = ex2f(f.x * CEXP);
        p[2 * h + 1] = ex2f(f.y * CEXP);
        sum += p[2 * h] + p[2 * h + 1];
        float2 fa2 = __half22float2(va2[h]);
        float2 fb2 = __half22float2(vb2[h]);
        vsum[2 * h] = fa2.x + fb2.x;
        vsum[2 * h + 1] = fa2.y + fb2.y;
    }
    sum += __shfl_xor_sync(0xFFFFFFFFu, sum, 1);
    float w = ew * rcpf(sum);

    float ctx[4];
#pragma unroll
    for (int i = 0; i < 4; i++) ctx[i] = p[i] * w * vsum[i];

    if (valid) {
        float* ap = g_acc + (size_t)d * O + c;
        asm volatile("red.global.add.v4.f32 [%0], {%1, %2, %3, %4};" ::"l"(ap),
                     "f"(ctx[0]), "f"(ctx[1]), "f"(ctx[2]), "f"(ctx[3])
                     : "memory");
        if (sub == 0) atomicAdd(&g_cnt[d], 1.0f);
    }
}

// ---------------- finalize (float4 per thread): mean/residual/relu -----------
// mode 0: g_x0 = rna(relu(acc/cnt)); mode 1: g_h1 = rna(relu(acc/cnt));
// mode 2: out = relu(acc/cnt + g_x0). Re-arms acc for modes 0/1.
__global__ void finalize_kernel(float* __restrict__ outp, int O, int mode) {
    int idx = blockIdx.x * blockDim.x + threadIdx.x;  // float4 index
    int total4 = NN * O / 4;
    if (idx >= total4) return;
    int u = idx / (O / 4);
    float inv = 1.0f / fmaxf(g_cnt[u], 1.0f);
    float4 a = ((float4*)g_acc)[idx];
    if (mode != 2) ((float4*)g_acc)[idx] = make_float4(0.f, 0.f, 0.f, 0.f);
    float vv[4] = {a.x * inv, a.y * inv, a.z * inv, a.w * inv};
    if (mode == 2) {
        float4 r = ((const float4*)g_x0)[idx];
        float4 o;
        o.x = fmaxf(vv[0] + r.x, 0.0f);
        o.y = fmaxf(vv[1] + r.y, 0.0f);
        o.z = fmaxf(vv[2] + r.z, 0.0f);
        o.w = fmaxf(vv[3] + r.w, 0.0f);
        ((float4*)outp)[idx] = o;
    } else {
        float4 o;
        o.x = rna_tf32(fmaxf(vv[0], 0.0f));
        o.y = rna_tf32(fmaxf(vv[1], 0.0f));
        o.z = rna_tf32(fmaxf(vv[2], 0.0f));
        o.w = rna_tf32(fmaxf(vv[3], 0.0f));
        if (mode == 0)
            ((float4*)g_x0)[idx] = o;
        else
            ((float4*)g_h1)[idx] = o;
    }
}

// ---------------- launch -----------------------------------------------------
extern "C" void kernel_launch(void* const* d_in, const int* in_sizes, int n_in,
                              void* d_out, int out_size) {
    const float* x = (const float*)d_in[0];
    const int* e0 = (const int*)d_in[1];
    const int* e1 = (const int*)d_in[2];
    const int* e2 = (const int*)d_in[3];
    const float* wq0 = (const float*)d_in[5];
    const float* bq0 = (const float*)d_in[6];
    const float* wk0 = (const float*)d_in[7];
    const float* bk0 = (const float*)d_in[8];
    const float* wv0 = (const float*)d_in[9];
    const float* bv0 = (const float*)d_in[10];
    const float* wq1 = (const float*)d_in[11];
    const float* bq1 = (const float*)d_in[12];
    const float* wk1 = (const float*)d_in[13];
    const float* bk1 = (const float*)d_in[14];
    const float* wv1 = (const float*)d_in[15];
    const float* bv1 = (const float*)d_in[16];
    const float* wq2 = (const float*)d_in[17];
    const float* bq2 = (const float*)d_in[18];
    const float* wk2 = (const float*)d_in[19];
    const float* bk2 = (const float*)d_in[20];
    const float* wv2 = (const float*)d_in[21];
    const float* bv2 = (const float*)d_in[22];

    int E0 = in_sizes[1] / 2;
    int E1 = in_sizes[2] / 2;
    int E2 = in_sizes[3] / 2;

    int fin4_128 = (NN * 128 / 4 + 255) / 256;
    int fin4_64 = (NN * 64 / 4 + 255) / 256;
    int nblk = (NN + 127) / 128;
    int bw0 = (128 * 768 + 255) / 256;
    int bw1 = max((128 * 384 + 255) / 256, (NN + 255) / 256);
    int bw2 = max((64 * 768 + 255) / 256, (NN + 255) / 256);

    zero_acc<<<fin4_128, 256>>>(NN * 128 / 4);  // one-time; finalize re-arms after

    // ---- Layer 0: C=128, O=128 ----
    build_wcat<<<bw0, 256>>>(wq0, wk0, wv0, bq0, bk0, bv0, 128, 128);
    mma_gemm<128, 128, true><<<dim3(6, nblk), 256>>>(x, 0, NN);
    edge_kernel128<<<(E0 + 7) / 8, 256>>>(e0, e0 + E0, E0);
    finalize_kernel<<<fin4_128, 256>>>(nullptr, 128, 0);

    // ---- Layer 1: C=128, O=64 ----
    build_wcat<<<bw1, 256>>>(wq1, wk1, wv1, bq1, bk1, bv1, 128, 64);
    mma_gemm<128, 64, false><<<dim3(3, nblk), 256>>>(nullptr, 1, NN);
    edge_kernel64<<<((E1 + 1) / 2 + 7) / 8, 256>>>(e1, e1 + E1, E1);
    finalize_kernel<<<fin4_64, 256>>>(nullptr, 64, 1);

    // ---- Layer 2: C=64, O=128 ----
    build_wcat<<<bw2, 256>>>(wq2, wk2, wv2, bq2, bk2, bv2, 64, 128);
    mma_gemm<64, 128, false><<<dim3(6, nblk), 256>>>(nullptr, 2, NN);
    edge_kernel128<<<(E2 + 7) / 8, 256>>>(e2, e2 + E2, E2);
    finalize_kernel<<<fin4_128, 256>>>((float*)d_out, 128, 2);
}